// round 5
// baseline (speedup 1.0000x reference)
#include <cuda_runtime.h>
#include <mma.h>
#include <cstdint>

#define NN 20000
#define EE 160000
#define E2 320000
#define HD 128

// ---------------- static scratch (no allocations allowed) ----------------
static __device__ float g_AB[2 * NN * HD];       // P | Q projections (contiguous for grid.z)
static __device__ float g_C[NN * HD];
static __device__ float g_H[NN * HD];
static __device__ float g_X[(size_t)NN * 512];   // [h | Lh | L^2h | L^3h]
static __device__ float g_h16[NN * 16];
static __device__ float g_degf[NN];
static __device__ float g_dis[NN];
static __device__ int   g_deg[NN];
static __device__ int   g_cnt[NN];
static __device__ int   g_off[NN + 1];
static __device__ int   g_csr_src[E2];
static __device__ int   g_csr_rid[E2];

// ---------------- fused mask MLP (+ zero g_deg) ----------------
// out[i] = relu(mask[i]@w1+b1)@w2 + b2 + x[i]      (one warp per node)
__global__ __launch_bounds__(256)
void k_mask(const float* __restrict__ mask, const float* __restrict__ x,
            const float* __restrict__ w1, const float* __restrict__ b1,
            const float* __restrict__ w2, const float* __restrict__ b2,
            float* __restrict__ out) {
    __shared__ float sw1[16 * 128];
    __shared__ float sb1[128];
    __shared__ float sw2[128 * 16];
    __shared__ float sb2[16];
    for (int v = threadIdx.x; v < 2048; v += blockDim.x) { sw1[v] = w1[v]; sw2[v] = w2[v]; }
    for (int v = threadIdx.x; v < 128; v += blockDim.x) sb1[v] = b1[v];
    if (threadIdx.x < 16) sb2[threadIdx.x] = b2[threadIdx.x];

    int gt = blockIdx.x * blockDim.x + threadIdx.x;
    if (gt < NN) g_deg[gt] = 0;            // histogram zeroing (used by k_hist later)
    __syncthreads();

    int i = gt >> 5;
    if (i >= NN) return;
    int lane = threadIdx.x & 31;
    int f = lane * 4;
    float m = (lane < 16) ? mask[(size_t)i * 16 + lane] : 0.0f;
    float4 h = *(const float4*)&sb1[f];
#pragma unroll
    for (int k = 0; k < 16; k++) {
        float a = __shfl_sync(0xffffffffu, m, k);
        const float4 w = *(const float4*)&sw1[k * 128 + f];
        h.x += a * w.x; h.y += a * w.y; h.z += a * w.z; h.w += a * w.w;
    }
    h.x = fmaxf(h.x, 0.f); h.y = fmaxf(h.y, 0.f);
    h.z = fmaxf(h.z, 0.f); h.w = fmaxf(h.w, 0.f);

    float o[16];
#pragma unroll
    for (int t = 0; t < 16; t++) o[t] = 0.0f;
    float hv[4] = {h.x, h.y, h.z, h.w};
#pragma unroll
    for (int j = 0; j < 4; j++) {
        const float* wrow = &sw2[(f + j) * 16];
        float hj = hv[j];
#pragma unroll
        for (int t = 0; t < 16; t++) o[t] += hj * wrow[t];
    }
#pragma unroll
    for (int off = 16; off > 0; off >>= 1)
#pragma unroll
        for (int t = 0; t < 16; t++) o[t] += __shfl_xor_sync(0xffffffffu, o[t], off);
    if (lane < 16)
        out[(size_t)i * 16 + lane] = o[lane] + sb2[lane] + x[(size_t)i * 16 + lane];
}

// ---------------- CSR build ----------------
__global__ void k_hist(const int* __restrict__ ei) {
    int e = blockIdx.x * blockDim.x + threadIdx.x;
    if (e >= EE) return;
    int s = ei[e], d = ei[EE + e];
    atomicAdd(&g_deg[d], 1);
    atomicAdd(&g_deg[s], 1);
}

__global__ void k_scan() {  // single block, 1024 threads; also zeroes g_cnt, fills degf/dis
    __shared__ int part[1024];
    const int CH = (NN + 1023) / 1024;  // 20
    int t = threadIdx.x;
    int base = t * CH;
    int s = 0;
    for (int j = 0; j < CH; j++) {
        int idx = base + j;
        if (idx < NN) s += g_deg[idx];
    }
    part[t] = s;
    __syncthreads();
    for (int off = 1; off < 1024; off <<= 1) {
        int v = (t >= off) ? part[t - off] : 0;
        __syncthreads();
        part[t] += v;
        __syncthreads();
    }
    int run = (t > 0) ? part[t - 1] : 0;
    for (int j = 0; j < CH; j++) {
        int idx = base + j;
        if (idx < NN) {
            g_off[idx] = run;
            int d = g_deg[idx];
            run += d;
            g_cnt[idx] = 0;
            g_degf[idx] = (float)d;
            g_dis[idx]  = (d > 0) ? rsqrtf((float)d) : 0.0f;
        }
    }
    if (t == 1023) g_off[NN] = run;
}

__global__ void k_fill(const int* __restrict__ ei) {
    int e = blockIdx.x * blockDim.x + threadIdx.x;
    if (e >= EE) return;
    int s0 = ei[e], d0 = ei[EE + e];
    int p = atomicAdd(&g_cnt[d0], 1);
    int slot = g_off[d0] + p;
    g_csr_src[slot] = s0;
    g_csr_rid[slot] = e;
    p = atomicAdd(&g_cnt[s0], 1);
    slot = g_off[s0] + p;
    g_csr_src[slot] = d0;
    g_csr_rid[slot] = e;
}

// ---------------- 3xTF32 tensor-core GEMM, 64x64 tile ----------------
// D[M,N] = A[M,K] @ B[K,N] (+Cin)(+rowscale*bias)(relu).
// Split hi/lo at smem-store time; inner loop: acc += al*bh + ah*bl + ah*bh.
// grid.z batches over (B += z*bStride, D += z*dStride).
__global__ __launch_bounds__(128)
void k_gemm_tc(const float* __restrict__ A, int lda,
               const float* __restrict__ B, long bStride,
               float* __restrict__ D, int ldd, long dStride,
               const float* __restrict__ Cin, int ldc,
               const float* __restrict__ bias, const float* __restrict__ rowscale,
               int M, int K, int N, int relu) {
    using namespace nvcuda;
    __shared__ float Ah[2][64 * 20], Al[2][64 * 20];
    __shared__ float Bh[2][16 * 72], Bl[2][16 * 72];

    B += (size_t)blockIdx.z * bStride;
    D += (size_t)blockIdx.z * dStride;

    int tid = threadIdx.x;
    int wid = tid >> 5, lane = tid & 31;
    int wm = wid >> 1, wn = wid & 1;
    int row0 = blockIdx.y * 64, col0 = blockIdx.x * 64;

    wmma::fragment<wmma::accumulator, 16, 16, 8, float> acc[2][2];
#pragma unroll
    for (int mi = 0; mi < 2; mi++)
#pragma unroll
        for (int ni = 0; ni < 2; ni++) wmma::fill_fragment(acc[mi][ni], 0.0f);

    int KT = K >> 4;

    auto split = [](float v, float& hi, float& lo) {
        hi = wmma::__float_to_tf32(v);
        lo = wmma::__float_to_tf32(v - hi);
    };
    auto loadA = [&](int kt, int buf) {
        int k0 = kt << 4;
#pragma unroll
        for (int i = 0; i < 2; i++) {
            int v = tid + (i << 7);
            int r = v >> 2, c = (v & 3) << 2;
            int gr = row0 + r;
            float4 a = make_float4(0.f, 0.f, 0.f, 0.f);
            if (gr < M) a = *(const float4*)(A + (size_t)gr * lda + k0 + c);
            float4 h, l;
            split(a.x, h.x, l.x); split(a.y, h.y, l.y);
            split(a.z, h.z, l.z); split(a.w, h.w, l.w);
            *(float4*)&Ah[buf][r * 20 + c] = h;
            *(float4*)&Al[buf][r * 20 + c] = l;
        }
    };
    auto loadB = [&](int kt, int buf) {
        int k0 = kt << 4;
#pragma unroll
        for (int i = 0; i < 2; i++) {
            int v = tid + (i << 7);
            int r = v >> 4, c = (v & 15) << 2;
            int gc = col0 + c;
            float4 b = make_float4(0.f, 0.f, 0.f, 0.f);
            if (gc < N) b = *(const float4*)(B + (size_t)(k0 + r) * N + gc);
            float4 h, l;
            split(b.x, h.x, l.x); split(b.y, h.y, l.y);
            split(b.z, h.z, l.z); split(b.w, h.w, l.w);
            *(float4*)&Bh[buf][r * 72 + c] = h;
            *(float4*)&Bl[buf][r * 72 + c] = l;
        }
    };

    loadA(0, 0); loadB(0, 0);
    __syncthreads();
    for (int kt = 0; kt < KT; kt++) {
        int buf = kt & 1;
        if (kt + 1 < KT) { loadA(kt + 1, buf ^ 1); loadB(kt + 1, buf ^ 1); }
#pragma unroll
        for (int ks = 0; ks < 2; ks++) {
            wmma::fragment<wmma::matrix_a, 16, 16, 8, wmma::precision::tf32, wmma::row_major> ah[2], al[2];
            wmma::fragment<wmma::matrix_b, 16, 16, 8, wmma::precision::tf32, wmma::row_major> bh[2], bl[2];
#pragma unroll
            for (int mi = 0; mi < 2; mi++) {
                wmma::load_matrix_sync(ah[mi], &Ah[buf][(wm * 32 + mi * 16) * 20 + ks * 8], 20);
                wmma::load_matrix_sync(al[mi], &Al[buf][(wm * 32 + mi * 16) * 20 + ks * 8], 20);
            }
#pragma unroll
            for (int ni = 0; ni < 2; ni++) {
                wmma::load_matrix_sync(bh[ni], &Bh[buf][(ks * 8) * 72 + wn * 32 + ni * 16], 72);
                wmma::load_matrix_sync(bl[ni], &Bl[buf][(ks * 8) * 72 + wn * 32 + ni * 16], 72);
            }
#pragma unroll
            for (int mi = 0; mi < 2; mi++)
#pragma unroll
                for (int ni = 0; ni < 2; ni++) {
                    wmma::mma_sync(acc[mi][ni], al[mi], bh[ni], acc[mi][ni]);
                    wmma::mma_sync(acc[mi][ni], ah[mi], bl[ni], acc[mi][ni]);
                    wmma::mma_sync(acc[mi][ni], ah[mi], bh[ni], acc[mi][ni]);
                }
        }
        __syncthreads();
    }

    // epilogue: per-warp staging in Ah[0]
    float* epi = &Ah[0][0] + wid * 320;
#pragma unroll
    for (int mi = 0; mi < 2; mi++) {
#pragma unroll
        for (int ni = 0; ni < 2; ni++) {
            wmma::store_matrix_sync(epi, acc[mi][ni], 20, wmma::mem_row_major);
            __syncwarp();
            int r = lane >> 1, cb = (lane & 1) * 8;
            int m = row0 + wm * 32 + mi * 16 + r;
            int n0 = col0 + wn * 32 + ni * 16 + cb;
            if (m < M && n0 < N) {
                float rs = rowscale ? rowscale[m] : 1.0f;
                float4 v0 = *(float4*)&epi[r * 20 + cb];
                float4 v1 = *(float4*)&epi[r * 20 + cb + 4];
                if (Cin) {
                    float4 c0 = *(const float4*)(Cin + (size_t)m * ldc + n0);
                    float4 c1 = *(const float4*)(Cin + (size_t)m * ldc + n0 + 4);
                    v0.x += c0.x; v0.y += c0.y; v0.z += c0.z; v0.w += c0.w;
                    v1.x += c1.x; v1.y += c1.y; v1.z += c1.z; v1.w += c1.w;
                }
                if (bias) {
                    float4 b0 = *(const float4*)(bias + n0);
                    float4 b1 = *(const float4*)(bias + n0 + 4);
                    v0.x += rs * b0.x; v0.y += rs * b0.y; v0.z += rs * b0.z; v0.w += rs * b0.w;
                    v1.x += rs * b1.x; v1.y += rs * b1.y; v1.z += rs * b1.z; v1.w += rs * b1.w;
                }
                if (relu) {
                    v0.x = fmaxf(v0.x, 0.f); v0.y = fmaxf(v0.y, 0.f);
                    v0.z = fmaxf(v0.z, 0.f); v0.w = fmaxf(v0.w, 0.f);
                    v1.x = fmaxf(v1.x, 0.f); v1.y = fmaxf(v1.y, 0.f);
                    v1.z = fmaxf(v1.z, 0.f); v1.w = fmaxf(v1.w, 0.f);
                }
                *(float4*)(D + (size_t)m * ldd + n0)     = v0;
                *(float4*)(D + (size_t)m * ldd + n0 + 4) = v1;
            }
            __syncwarp();
        }
    }
}

// ---------------- fused EA edge pass ----------------
// S[i] = sum_neighbors relu( P[i] + Q[src] + (ea[rid] @ W1e + b1) )
__global__ __launch_bounds__(256)
void k_edge_f(const float* __restrict__ P, const float* __restrict__ Q,
              const float* __restrict__ EA, const float* __restrict__ W1e,
              const float* __restrict__ b1, float* __restrict__ S) {
    __shared__ float sw[16 * 128];
    __shared__ float sb[128];
    for (int v = threadIdx.x; v < 2048; v += blockDim.x) sw[v] = W1e[v];
    for (int v = threadIdx.x; v < 128; v += blockDim.x) sb[v] = b1[v];
    __syncthreads();
    int lane = threadIdx.x & 31;
    int f = lane * 4;
    float w[16][4];
#pragma unroll
    for (int k = 0; k < 16; k++) {
        float4 t = *(const float4*)&sw[k * 128 + f];
        w[k][0] = t.x; w[k][1] = t.y; w[k][2] = t.z; w[k][3] = t.w;
    }
    float4 bb = *(const float4*)&sb[f];

    int i = (blockIdx.x * blockDim.x + threadIdx.x) >> 5;
    if (i >= NN) return;
    float4 p = *(const float4*)(P + (size_t)i * HD + f);
    float4 acc = make_float4(0.f, 0.f, 0.f, 0.f);
    int s1 = g_off[i + 1];
    for (int s = g_off[i]; s < s1; s++) {
        int src = g_csr_src[s];
        int rid = g_csr_rid[s];
        float val = (lane < 16) ? EA[(size_t)rid * 16 + lane] : 0.0f;
        float4 q = *(const float4*)(Q + (size_t)src * HD + f);
        float4 r = bb;
#pragma unroll
        for (int k = 0; k < 16; k++) {
            float a = __shfl_sync(0xffffffffu, val, k);
            r.x += a * w[k][0]; r.y += a * w[k][1];
            r.z += a * w[k][2]; r.w += a * w[k][3];
        }
        acc.x += fmaxf(p.x + q.x + r.x, 0.f);
        acc.y += fmaxf(p.y + q.y + r.y, 0.f);
        acc.z += fmaxf(p.z + q.z + r.z, 0.f);
        acc.w += fmaxf(p.w + q.w + r.w, 0.f);
    }
    *(float4*)(S + (size_t)i * HD + f) = acc;
}

// ---------------- TAG propagation (norm folded via dis) ----------------
// Xn[i] = dis[i] * sum_neighbors dis[src] * Xc[src]      (ld = 512)
__global__ __launch_bounds__(256)
void k_prop(const float* __restrict__ Xc, float* __restrict__ Xn) {
    int i = (blockIdx.x * blockDim.x + threadIdx.x) >> 5;
    if (i >= NN) return;
    int lane = threadIdx.x & 31;
    int f = lane * 4;
    float4 acc = make_float4(0.f, 0.f, 0.f, 0.f);
    int s1 = g_off[i + 1];
    for (int s = g_off[i]; s < s1; s++) {
        int src = g_csr_src[s];
        float nm = __ldg(&g_dis[src]);
        float4 h = *(const float4*)(Xc + (size_t)src * 512 + f);
        acc.x += nm * h.x; acc.y += nm * h.y;
        acc.z += nm * h.z; acc.w += nm * h.w;
    }
    float di = __ldg(&g_dis[i]);
    acc.x *= di; acc.y *= di; acc.z *= di; acc.w *= di;
    *(float4*)(Xn + (size_t)i * 512 + f) = acc;
}

// ---------------- host ----------------
static void gemm(const float* A, int lda, const float* B, long bStride,
                 float* D, int ldd, long dStride,
                 const float* Cin, int ldc, const float* bias, const float* rowscale,
                 int M, int K, int N, int relu, int batch) {
    dim3 grid((N + 63) / 64, (M + 63) / 64, batch);
    k_gemm_tc<<<grid, 128>>>(A, lda, B, bStride, D, ldd, dStride,
                             Cin, ldc, bias, rowscale, M, K, N, relu);
}

extern "C" void kernel_launch(void* const* d_in, const int* in_sizes, int n_in,
                              void* d_out, int out_size) {
    const float* x         = (const float*)d_in[0];
    const float* mask      = (const float*)d_in[1];
    const float* edge_attr = (const float*)d_in[2];
    const int* edge_index;
    int base;
    if (in_sizes[3] == 2 * EE) {           // setup_inputs dict order
        edge_index = (const int*)d_in[3];
        base = 4;
    } else {                               // reference-signature order (edge_index last)
        edge_index = (const int*)d_in[n_in - 1];
        base = 3;
    }
    const float* m_w1   = (const float*)d_in[base + 0];
    const float* m_b1   = (const float*)d_in[base + 1];
    const float* m_w2   = (const float*)d_in[base + 2];
    const float* m_b2   = (const float*)d_in[base + 3];
    const float* ea0_w1 = (const float*)d_in[base + 4];
    const float* ea0_b1 = (const float*)d_in[base + 5];
    const float* ea0_w2 = (const float*)d_in[base + 6];
    const float* ea0_b2 = (const float*)d_in[base + 7];
    const float* tag0_w = (const float*)d_in[base + 8];
    const float* tag0_b = (const float*)d_in[base + 9];
    const float* ea1_w1 = (const float*)d_in[base + 10];
    const float* ea1_b1 = (const float*)d_in[base + 11];
    const float* ea1_w2 = (const float*)d_in[base + 12];
    const float* ea1_b2 = (const float*)d_in[base + 13];
    const float* tag1_w = (const float*)d_in[base + 14];
    const float* tag1_b = (const float*)d_in[base + 15];
    const float* ea2_w1 = (const float*)d_in[base + 16];
    const float* ea2_b1 = (const float*)d_in[base + 17];
    const float* ea2_w2 = (const float*)d_in[base + 18];
    const float* ea2_b2 = (const float*)d_in[base + 19];

    float *pAB, *pC, *pH, *pX, *ph16, *pdegf;
    cudaGetSymbolAddress((void**)&pAB, g_AB);
    cudaGetSymbolAddress((void**)&pC, g_C);
    cudaGetSymbolAddress((void**)&pH, g_H);
    cudaGetSymbolAddress((void**)&pX, g_X);
    cudaGetSymbolAddress((void**)&ph16, g_h16);
    cudaGetSymbolAddress((void**)&pdegf, g_degf);
    float* pA = pAB;
    float* pB = pAB + (size_t)NN * HD;

    const int EB = 2500;              // 20000 node-warps / 8 warps per block
    const long NSTR = (long)NN * HD;  // batch stride for projections

    // launches 0-3: mask MLP (+deg zeroing), CSR build
    k_mask<<<EB, 256>>>(mask, x, m_w1, m_b1, m_w2, m_b2, ph16);
    k_hist<<<(EE + 255) / 256, 256>>>(edge_index);
    k_scan<<<1, 1024>>>();
    k_fill<<<(EE + 255) / 256, 256>>>(edge_index);

    // ---- EA0 (in=16) ----
    gemm(ph16, 16, ea0_w1, 16 * 128, pAB, 128, NSTR, nullptr, 0, nullptr, nullptr,
         NN, 16, 128, 0, 2);                                        // launch 4
    k_edge_f<<<EB, 256>>>(pA, pB, edge_attr, ea0_w1 + 32 * 128, ea0_b1, pC);  // launch 5 (ncu)
    gemm(pC, 128, ea0_w2, 0, pX, 512, 0, nullptr, 0, ea0_b2, pdegf, NN, 128, 128, 1, 1);

    // ---- TAG0: props fill X slices, one K=512 GEMM ----
    k_prop<<<EB, 256>>>(pX,       pX + 128);
    k_prop<<<EB, 256>>>(pX + 128, pX + 256);
    k_prop<<<EB, 256>>>(pX + 256, pX + 384);
    gemm(pX, 512, tag0_w, 0, pH, 128, 0, nullptr, 0, tag0_b, nullptr, NN, 512, 128, 1, 1);

    // ---- EA1 (in=128) ----
    gemm(pH, 128, ea1_w1, 128 * 128, pAB, 128, NSTR, nullptr, 0, nullptr, nullptr,
         NN, 128, 128, 0, 2);
    k_edge_f<<<EB, 256>>>(pA, pB, edge_attr, ea1_w1 + 256 * 128, ea1_b1, pC);
    gemm(pC, 128, ea1_w2, 0, pX, 512, 0, nullptr, 0, ea1_b2, pdegf, NN, 128, 128, 1, 1);

    // ---- TAG1 ----
    k_prop<<<EB, 256>>>(pX,       pX + 128);
    k_prop<<<EB, 256>>>(pX + 128, pX + 256);
    k_prop<<<EB, 256>>>(pX + 256, pX + 384);
    gemm(pX, 512, tag1_w, 0, pH, 128, 0, nullptr, 0, tag1_b, nullptr, NN, 512, 128, 1, 1);

    // ---- EA2 (final, no relu, out = [N,16]) ----
    gemm(pH, 128, ea2_w1, 128 * 128, pAB, 128, NSTR, nullptr, 0, nullptr, nullptr,
         NN, 128, 128, 0, 2);
    k_edge_f<<<EB, 256>>>(pA, pB, edge_attr, ea2_w1 + 256 * 128, ea2_b1, pC);
    gemm(pC, 128, ea2_w2, 0, (float*)d_out, 16, 0, nullptr, 0, ea2_b2, pdegf,
         NN, 128, 16, 0, 1);
}

// round 6
// speedup vs baseline: 1.0020x; 1.0020x over previous
#include <cuda_runtime.h>
#include <mma.h>
#include <cstdint>

#define NN 20000
#define EE 160000
#define E2 320000
#define HD 128

// ---------------- static scratch (no allocations allowed) ----------------
static __device__ float g_AB[2 * NN * HD];       // P | Q projections (contiguous for grid.z)
static __device__ float g_C[NN * HD];
static __device__ float g_H[NN * HD];
static __device__ float g_X[(size_t)NN * 512];   // [h | Lh | L^2h | L^3h]
static __device__ float g_h16[NN * 16];
static __device__ float g_degf[NN];
static __device__ float g_dis[NN];
static __device__ int   g_deg[NN];
static __device__ int   g_cnt[NN];
static __device__ int   g_off[NN + 1];
static __device__ int   g_csr_src[E2];
static __device__ int   g_csr_rid[E2];

// ---------------- fused mask MLP (+ zero g_deg) ----------------
// out[i] = relu(mask[i]@w1+b1)@w2 + b2 + x[i]      (one warp per node)
__global__ __launch_bounds__(256)
void k_mask(const float* __restrict__ mask, const float* __restrict__ x,
            const float* __restrict__ w1, const float* __restrict__ b1,
            const float* __restrict__ w2, const float* __restrict__ b2,
            float* __restrict__ out) {
    __shared__ float sw1[16 * 128];
    __shared__ float sb1[128];
    __shared__ float sw2[128 * 16];
    __shared__ float sb2[16];
    for (int v = threadIdx.x; v < 2048; v += blockDim.x) { sw1[v] = w1[v]; sw2[v] = w2[v]; }
    for (int v = threadIdx.x; v < 128; v += blockDim.x) sb1[v] = b1[v];
    if (threadIdx.x < 16) sb2[threadIdx.x] = b2[threadIdx.x];

    int gt = blockIdx.x * blockDim.x + threadIdx.x;
    if (gt < NN) g_deg[gt] = 0;            // histogram zeroing (used by k_hist later)
    __syncthreads();

    int i = gt >> 5;
    if (i >= NN) return;
    int lane = threadIdx.x & 31;
    int f = lane * 4;
    float m = (lane < 16) ? mask[(size_t)i * 16 + lane] : 0.0f;
    float4 h = *(const float4*)&sb1[f];
#pragma unroll
    for (int k = 0; k < 16; k++) {
        float a = __shfl_sync(0xffffffffu, m, k);
        const float4 w = *(const float4*)&sw1[k * 128 + f];
        h.x += a * w.x; h.y += a * w.y; h.z += a * w.z; h.w += a * w.w;
    }
    h.x = fmaxf(h.x, 0.f); h.y = fmaxf(h.y, 0.f);
    h.z = fmaxf(h.z, 0.f); h.w = fmaxf(h.w, 0.f);

    float o[16];
#pragma unroll
    for (int t = 0; t < 16; t++) o[t] = 0.0f;
    float hv[4] = {h.x, h.y, h.z, h.w};
#pragma unroll
    for (int j = 0; j < 4; j++) {
        const float* wrow = &sw2[(f + j) * 16];
        float hj = hv[j];
#pragma unroll
        for (int t = 0; t < 16; t++) o[t] += hj * wrow[t];
    }
#pragma unroll
    for (int off = 16; off > 0; off >>= 1)
#pragma unroll
        for (int t = 0; t < 16; t++) o[t] += __shfl_xor_sync(0xffffffffu, o[t], off);
    if (lane < 16)
        out[(size_t)i * 16 + lane] = o[lane] + sb2[lane] + x[(size_t)i * 16 + lane];
}

// ---------------- CSR build ----------------
__global__ void k_hist(const int* __restrict__ ei) {
    int e = blockIdx.x * blockDim.x + threadIdx.x;
    if (e >= EE) return;
    int s = ei[e], d = ei[EE + e];
    atomicAdd(&g_deg[d], 1);
    atomicAdd(&g_deg[s], 1);
}

__global__ void k_scan() {  // single block, 1024 threads; also zeroes g_cnt, fills degf/dis
    __shared__ int part[1024];
    const int CH = (NN + 1023) / 1024;  // 20
    int t = threadIdx.x;
    int base = t * CH;
    int s = 0;
    for (int j = 0; j < CH; j++) {
        int idx = base + j;
        if (idx < NN) s += g_deg[idx];
    }
    part[t] = s;
    __syncthreads();
    for (int off = 1; off < 1024; off <<= 1) {
        int v = (t >= off) ? part[t - off] : 0;
        __syncthreads();
        part[t] += v;
        __syncthreads();
    }
    int run = (t > 0) ? part[t - 1] : 0;
    for (int j = 0; j < CH; j++) {
        int idx = base + j;
        if (idx < NN) {
            g_off[idx] = run;
            int d = g_deg[idx];
            run += d;
            g_cnt[idx] = 0;
            g_degf[idx] = (float)d;
            g_dis[idx]  = (d > 0) ? rsqrtf((float)d) : 0.0f;
        }
    }
    if (t == 1023) g_off[NN] = run;
}

__global__ void k_fill(const int* __restrict__ ei) {
    int e = blockIdx.x * blockDim.x + threadIdx.x;
    if (e >= EE) return;
    int s0 = ei[e], d0 = ei[EE + e];
    int p = atomicAdd(&g_cnt[d0], 1);
    int slot = g_off[d0] + p;
    g_csr_src[slot] = s0;
    g_csr_rid[slot] = e;
    p = atomicAdd(&g_cnt[s0], 1);
    slot = g_off[s0] + p;
    g_csr_src[slot] = d0;
    g_csr_rid[slot] = e;
}

// ---------------- 3xTF32 tensor-core GEMM, 64x64 tile ----------------
// D[M,N] = A[M,K] @ B[K,N] (+Cin)(+rowscale*bias)(relu).
// Split hi/lo at smem-store time; inner loop: acc += al*bh + ah*bl + ah*bh.
// grid.z batches over (B += z*bStride, D += z*dStride).
__global__ __launch_bounds__(128)
void k_gemm_tc(const float* __restrict__ A, int lda,
               const float* __restrict__ B, long bStride,
               float* __restrict__ D, int ldd, long dStride,
               const float* __restrict__ Cin, int ldc,
               const float* __restrict__ bias, const float* __restrict__ rowscale,
               int M, int K, int N, int relu) {
    using namespace nvcuda;
    __shared__ float Ah[2][64 * 20], Al[2][64 * 20];
    __shared__ float Bh[2][16 * 72], Bl[2][16 * 72];

    B += (size_t)blockIdx.z * bStride;
    D += (size_t)blockIdx.z * dStride;

    int tid = threadIdx.x;
    int wid = tid >> 5, lane = tid & 31;
    int wm = wid >> 1, wn = wid & 1;
    int row0 = blockIdx.y * 64, col0 = blockIdx.x * 64;

    wmma::fragment<wmma::accumulator, 16, 16, 8, float> acc[2][2];
#pragma unroll
    for (int mi = 0; mi < 2; mi++)
#pragma unroll
        for (int ni = 0; ni < 2; ni++) wmma::fill_fragment(acc[mi][ni], 0.0f);

    int KT = K >> 4;

    auto split = [](float v, float& hi, float& lo) {
        hi = wmma::__float_to_tf32(v);
        lo = wmma::__float_to_tf32(v - hi);
    };
    auto loadA = [&](int kt, int buf) {
        int k0 = kt << 4;
#pragma unroll
        for (int i = 0; i < 2; i++) {
            int v = tid + (i << 7);
            int r = v >> 2, c = (v & 3) << 2;
            int gr = row0 + r;
            float4 a = make_float4(0.f, 0.f, 0.f, 0.f);
            if (gr < M) a = *(const float4*)(A + (size_t)gr * lda + k0 + c);
            float4 h, l;
            split(a.x, h.x, l.x); split(a.y, h.y, l.y);
            split(a.z, h.z, l.z); split(a.w, h.w, l.w);
            *(float4*)&Ah[buf][r * 20 + c] = h;
            *(float4*)&Al[buf][r * 20 + c] = l;
        }
    };
    auto loadB = [&](int kt, int buf) {
        int k0 = kt << 4;
#pragma unroll
        for (int i = 0; i < 2; i++) {
            int v = tid + (i << 7);
            int r = v >> 4, c = (v & 15) << 2;
            int gc = col0 + c;
            float4 b = make_float4(0.f, 0.f, 0.f, 0.f);
            if (gc < N) b = *(const float4*)(B + (size_t)(k0 + r) * N + gc);
            float4 h, l;
            split(b.x, h.x, l.x); split(b.y, h.y, l.y);
            split(b.z, h.z, l.z); split(b.w, h.w, l.w);
            *(float4*)&Bh[buf][r * 72 + c] = h;
            *(float4*)&Bl[buf][r * 72 + c] = l;
        }
    };

    loadA(0, 0); loadB(0, 0);
    __syncthreads();
    for (int kt = 0; kt < KT; kt++) {
        int buf = kt & 1;
        if (kt + 1 < KT) { loadA(kt + 1, buf ^ 1); loadB(kt + 1, buf ^ 1); }
#pragma unroll
        for (int ks = 0; ks < 2; ks++) {
            wmma::fragment<wmma::matrix_a, 16, 16, 8, wmma::precision::tf32, wmma::row_major> ah[2], al[2];
            wmma::fragment<wmma::matrix_b, 16, 16, 8, wmma::precision::tf32, wmma::row_major> bh[2], bl[2];
#pragma unroll
            for (int mi = 0; mi < 2; mi++) {
                wmma::load_matrix_sync(ah[mi], &Ah[buf][(wm * 32 + mi * 16) * 20 + ks * 8], 20);
                wmma::load_matrix_sync(al[mi], &Al[buf][(wm * 32 + mi * 16) * 20 + ks * 8], 20);
            }
#pragma unroll
            for (int ni = 0; ni < 2; ni++) {
                wmma::load_matrix_sync(bh[ni], &Bh[buf][(ks * 8) * 72 + wn * 32 + ni * 16], 72);
                wmma::load_matrix_sync(bl[ni], &Bl[buf][(ks * 8) * 72 + wn * 32 + ni * 16], 72);
            }
#pragma unroll
            for (int mi = 0; mi < 2; mi++)
#pragma unroll
                for (int ni = 0; ni < 2; ni++) {
                    wmma::mma_sync(acc[mi][ni], al[mi], bh[ni], acc[mi][ni]);
                    wmma::mma_sync(acc[mi][ni], ah[mi], bl[ni], acc[mi][ni]);
                    wmma::mma_sync(acc[mi][ni], ah[mi], bh[ni], acc[mi][ni]);
                }
        }
        __syncthreads();
    }

    // epilogue: per-warp staging in Ah[0]
    float* epi = &Ah[0][0] + wid * 320;
#pragma unroll
    for (int mi = 0; mi < 2; mi++) {
#pragma unroll
        for (int ni = 0; ni < 2; ni++) {
            wmma::store_matrix_sync(epi, acc[mi][ni], 20, wmma::mem_row_major);
            __syncwarp();
            int r = lane >> 1, cb = (lane & 1) * 8;
            int m = row0 + wm * 32 + mi * 16 + r;
            int n0 = col0 + wn * 32 + ni * 16 + cb;
            if (m < M && n0 < N) {
                float rs = rowscale ? rowscale[m] : 1.0f;
                float4 v0 = *(float4*)&epi[r * 20 + cb];
                float4 v1 = *(float4*)&epi[r * 20 + cb + 4];
                if (Cin) {
                    float4 c0 = *(const float4*)(Cin + (size_t)m * ldc + n0);
                    float4 c1 = *(const float4*)(Cin + (size_t)m * ldc + n0 + 4);
                    v0.x += c0.x; v0.y += c0.y; v0.z += c0.z; v0.w += c0.w;
                    v1.x += c1.x; v1.y += c1.y; v1.z += c1.z; v1.w += c1.w;
                }
                if (bias) {
                    float4 b0 = *(const float4*)(bias + n0);
                    float4 b1 = *(const float4*)(bias + n0 + 4);
                    v0.x += rs * b0.x; v0.y += rs * b0.y; v0.z += rs * b0.z; v0.w += rs * b0.w;
                    v1.x += rs * b1.x; v1.y += rs * b1.y; v1.z += rs * b1.z; v1.w += rs * b1.w;
                }
                if (relu) {
                    v0.x = fmaxf(v0.x, 0.f); v0.y = fmaxf(v0.y, 0.f);
                    v0.z = fmaxf(v0.z, 0.f); v0.w = fmaxf(v0.w, 0.f);
                    v1.x = fmaxf(v1.x, 0.f); v1.y = fmaxf(v1.y, 0.f);
                    v1.z = fmaxf(v1.z, 0.f); v1.w = fmaxf(v1.w, 0.f);
                }
                *(float4*)(D + (size_t)m * ldd + n0)     = v0;
                *(float4*)(D + (size_t)m * ldd + n0 + 4) = v1;
            }
            __syncwarp();
        }
    }
}

// ---------------- fused EA edge pass ----------------
// S[i] = sum_neighbors relu( P[i] + Q[src] + (ea[rid] @ W1e + b1) )
__global__ __launch_bounds__(256)
void k_edge_f(const float* __restrict__ P, const float* __restrict__ Q,
              const float* __restrict__ EA, const float* __restrict__ W1e,
              const float* __restrict__ b1, float* __restrict__ S) {
    __shared__ float sw[16 * 128];
    __shared__ float sb[128];
    for (int v = threadIdx.x; v < 2048; v += blockDim.x) sw[v] = W1e[v];
    for (int v = threadIdx.x; v < 128; v += blockDim.x) sb[v] = b1[v];
    __syncthreads();
    int lane = threadIdx.x & 31;
    int f = lane * 4;
    float w[16][4];
#pragma unroll
    for (int k = 0; k < 16; k++) {
        float4 t = *(const float4*)&sw[k * 128 + f];
        w[k][0] = t.x; w[k][1] = t.y; w[k][2] = t.z; w[k][3] = t.w;
    }
    float4 bb = *(const float4*)&sb[f];

    int i = (blockIdx.x * blockDim.x + threadIdx.x) >> 5;
    if (i >= NN) return;
    float4 p = *(const float4*)(P + (size_t)i * HD + f);
    float4 acc = make_float4(0.f, 0.f, 0.f, 0.f);
    int s1 = g_off[i + 1];
    for (int s = g_off[i]; s < s1; s++) {
        int src = g_csr_src[s];
        int rid = g_csr_rid[s];
        float val = (lane < 16) ? EA[(size_t)rid * 16 + lane] : 0.0f;
        float4 q = *(const float4*)(Q + (size_t)src * HD + f);
        float4 r = bb;
#pragma unroll
        for (int k = 0; k < 16; k++) {
            float a = __shfl_sync(0xffffffffu, val, k);
            r.x += a * w[k][0]; r.y += a * w[k][1];
            r.z += a * w[k][2]; r.w += a * w[k][3];
        }
        acc.x += fmaxf(p.x + q.x + r.x, 0.f);
        acc.y += fmaxf(p.y + q.y + r.y, 0.f);
        acc.z += fmaxf(p.z + q.z + r.z, 0.f);
        acc.w += fmaxf(p.w + q.w + r.w, 0.f);
    }
    *(float4*)(S + (size_t)i * HD + f) = acc;
}

// ---------------- TAG propagation (norm folded via dis) ----------------
// Xn[i] = dis[i] * sum_neighbors dis[src] * Xc[src]      (ld = 512)
__global__ __launch_bounds__(256)
void k_prop(const float* __restrict__ Xc, float* __restrict__ Xn) {
    int i = (blockIdx.x * blockDim.x + threadIdx.x) >> 5;
    if (i >= NN) return;
    int lane = threadIdx.x & 31;
    int f = lane * 4;
    float4 acc = make_float4(0.f, 0.f, 0.f, 0.f);
    int s1 = g_off[i + 1];
    for (int s = g_off[i]; s < s1; s++) {
        int src = g_csr_src[s];
        float nm = __ldg(&g_dis[src]);
        float4 h = *(const float4*)(Xc + (size_t)src * 512 + f);
        acc.x += nm * h.x; acc.y += nm * h.y;
        acc.z += nm * h.z; acc.w += nm * h.w;
    }
    float di = __ldg(&g_dis[i]);
    acc.x *= di; acc.y *= di; acc.z *= di; acc.w *= di;
    *(float4*)(Xn + (size_t)i * 512 + f) = acc;
}

// ---------------- host ----------------
static void gemm(const float* A, int lda, const float* B, long bStride,
                 float* D, int ldd, long dStride,
                 const float* Cin, int ldc, const float* bias, const float* rowscale,
                 int M, int K, int N, int relu, int batch) {
    dim3 grid((N + 63) / 64, (M + 63) / 64, batch);
    k_gemm_tc<<<grid, 128>>>(A, lda, B, bStride, D, ldd, dStride,
                             Cin, ldc, bias, rowscale, M, K, N, relu);
}

extern "C" void kernel_launch(void* const* d_in, const int* in_sizes, int n_in,
                              void* d_out, int out_size) {
    const float* x         = (const float*)d_in[0];
    const float* mask      = (const float*)d_in[1];
    const float* edge_attr = (const float*)d_in[2];
    const int* edge_index;
    int base;
    if (in_sizes[3] == 2 * EE) {           // setup_inputs dict order
        edge_index = (const int*)d_in[3];
        base = 4;
    } else {                               // reference-signature order (edge_index last)
        edge_index = (const int*)d_in[n_in - 1];
        base = 3;
    }
    const float* m_w1   = (const float*)d_in[base + 0];
    const float* m_b1   = (const float*)d_in[base + 1];
    const float* m_w2   = (const float*)d_in[base + 2];
    const float* m_b2   = (const float*)d_in[base + 3];
    const float* ea0_w1 = (const float*)d_in[base + 4];
    const float* ea0_b1 = (const float*)d_in[base + 5];
    const float* ea0_w2 = (const float*)d_in[base + 6];
    const float* ea0_b2 = (const float*)d_in[base + 7];
    const float* tag0_w = (const float*)d_in[base + 8];
    const float* tag0_b = (const float*)d_in[base + 9];
    const float* ea1_w1 = (const float*)d_in[base + 10];
    const float* ea1_b1 = (const float*)d_in[base + 11];
    const float* ea1_w2 = (const float*)d_in[base + 12];
    const float* ea1_b2 = (const float*)d_in[base + 13];
    const float* tag1_w = (const float*)d_in[base + 14];
    const float* tag1_b = (const float*)d_in[base + 15];
    const float* ea2_w1 = (const float*)d_in[base + 16];
    const float* ea2_b1 = (const float*)d_in[base + 17];
    const float* ea2_w2 = (const float*)d_in[base + 18];
    const float* ea2_b2 = (const float*)d_in[base + 19];

    float *pAB, *pC, *pH, *pX, *ph16, *pdegf;
    cudaGetSymbolAddress((void**)&pAB, g_AB);
    cudaGetSymbolAddress((void**)&pC, g_C);
    cudaGetSymbolAddress((void**)&pH, g_H);
    cudaGetSymbolAddress((void**)&pX, g_X);
    cudaGetSymbolAddress((void**)&ph16, g_h16);
    cudaGetSymbolAddress((void**)&pdegf, g_degf);
    float* pA = pAB;
    float* pB = pAB + (size_t)NN * HD;

    const int EB = 2500;              // 20000 node-warps / 8 warps per block
    const long NSTR = (long)NN * HD;  // batch stride for projections

    // launches 0-3: mask MLP (+deg zeroing), CSR build
    k_mask<<<EB, 256>>>(mask, x, m_w1, m_b1, m_w2, m_b2, ph16);
    k_hist<<<(EE + 255) / 256, 256>>>(edge_index);
    k_scan<<<1, 1024>>>();
    k_fill<<<(EE + 255) / 256, 256>>>(edge_index);

    // ---- EA0 (in=16) ----
    gemm(ph16, 16, ea0_w1, 16 * 128, pAB, 128, NSTR, nullptr, 0, nullptr, nullptr,
         NN, 16, 128, 0, 2);                                        // launch 4
    k_edge_f<<<EB, 256>>>(pA, pB, edge_attr, ea0_w1 + 32 * 128, ea0_b1, pC);  // launch 5 (ncu)
    gemm(pC, 128, ea0_w2, 0, pX, 512, 0, nullptr, 0, ea0_b2, pdegf, NN, 128, 128, 1, 1);

    // ---- TAG0: props fill X slices, one K=512 GEMM ----
    k_prop<<<EB, 256>>>(pX,       pX + 128);
    k_prop<<<EB, 256>>>(pX + 128, pX + 256);
    k_prop<<<EB, 256>>>(pX + 256, pX + 384);
    gemm(pX, 512, tag0_w, 0, pH, 128, 0, nullptr, 0, tag0_b, nullptr, NN, 512, 128, 1, 1);

    // ---- EA1 (in=128) ----
    gemm(pH, 128, ea1_w1, 128 * 128, pAB, 128, NSTR, nullptr, 0, nullptr, nullptr,
         NN, 128, 128, 0, 2);
    k_edge_f<<<EB, 256>>>(pA, pB, edge_attr, ea1_w1 + 256 * 128, ea1_b1, pC);
    gemm(pC, 128, ea1_w2, 0, pX, 512, 0, nullptr, 0, ea1_b2, pdegf, NN, 128, 128, 1, 1);

    // ---- TAG1 ----
    k_prop<<<EB, 256>>>(pX,       pX + 128);
    k_prop<<<EB, 256>>>(pX + 128, pX + 256);
    k_prop<<<EB, 256>>>(pX + 256, pX + 384);
    gemm(pX, 512, tag1_w, 0, pH, 128, 0, nullptr, 0, tag1_b, nullptr, NN, 512, 128, 1, 1);

    // ---- EA2 (final, no relu, out = [N,16]) ----
    gemm(pH, 128, ea2_w1, 128 * 128, pAB, 128, NSTR, nullptr, 0, nullptr, nullptr,
         NN, 128, 128, 0, 2);
    k_edge_f<<<EB, 256>>>(pA, pB, edge_attr, ea2_w1 + 256 * 128, ea2_b1, pC);
    gemm(pC, 128, ea2_w2, 0, (float*)d_out, 16, 0, nullptr, 0, ea2_b2, pdegf,
         NN, 128, 16, 0, 1);
}

// round 7
// speedup vs baseline: 1.0041x; 1.0021x over previous
#include <cuda_runtime.h>
#include <mma.h>
#include <cstdint>

#define NN 20000
#define EE 160000
#define E2 320000
#define HD 128

// ---------------- static scratch (no allocations allowed) ----------------
static __device__ float g_AB[2 * NN * HD];       // P | Q projections (contiguous for grid.z)
static __device__ float g_C[NN * HD];
static __device__ float g_H[NN * HD];
static __device__ float g_X[(size_t)NN * 512];   // [h | Lh | L^2h | L^3h]
static __device__ float g_h16[NN * 16];
static __device__ float g_degf[NN];
static __device__ float g_dis[NN];
static __device__ int   g_deg[NN];
static __device__ int   g_cnt[NN];
static __device__ int   g_off[NN + 1];
static __device__ int   g_csr_src[E2];
static __device__ int   g_csr_rid[E2];

// ---------------- fused mask MLP (+ zero g_deg) ----------------
// out[i] = relu(mask[i]@w1+b1)@w2 + b2 + x[i]      (one warp per node)
__global__ __launch_bounds__(256)
void k_mask(const float* __restrict__ mask, const float* __restrict__ x,
            const float* __restrict__ w1, const float* __restrict__ b1,
            const float* __restrict__ w2, const float* __restrict__ b2,
            float* __restrict__ out) {
    __shared__ float sw1[16 * 128];
    __shared__ float sb1[128];
    __shared__ float sw2[128 * 16];
    __shared__ float sb2[16];
    for (int v = threadIdx.x; v < 2048; v += blockDim.x) { sw1[v] = w1[v]; sw2[v] = w2[v]; }
    for (int v = threadIdx.x; v < 128; v += blockDim.x) sb1[v] = b1[v];
    if (threadIdx.x < 16) sb2[threadIdx.x] = b2[threadIdx.x];

    int gt = blockIdx.x * blockDim.x + threadIdx.x;
    if (gt < NN) g_deg[gt] = 0;            // histogram zeroing (used by k_hist later)
    __syncthreads();

    int i = gt >> 5;
    if (i >= NN) return;
    int lane = threadIdx.x & 31;
    int f = lane * 4;
    float m = (lane < 16) ? mask[(size_t)i * 16 + lane] : 0.0f;
    float4 h = *(const float4*)&sb1[f];
#pragma unroll
    for (int k = 0; k < 16; k++) {
        float a = __shfl_sync(0xffffffffu, m, k);
        const float4 w = *(const float4*)&sw1[k * 128 + f];
        h.x += a * w.x; h.y += a * w.y; h.z += a * w.z; h.w += a * w.w;
    }
    h.x = fmaxf(h.x, 0.f); h.y = fmaxf(h.y, 0.f);
    h.z = fmaxf(h.z, 0.f); h.w = fmaxf(h.w, 0.f);

    float o[16];
#pragma unroll
    for (int t = 0; t < 16; t++) o[t] = 0.0f;
    float hv[4] = {h.x, h.y, h.z, h.w};
#pragma unroll
    for (int j = 0; j < 4; j++) {
        const float* wrow = &sw2[(f + j) * 16];
        float hj = hv[j];
#pragma unroll
        for (int t = 0; t < 16; t++) o[t] += hj * wrow[t];
    }
#pragma unroll
    for (int off = 16; off > 0; off >>= 1)
#pragma unroll
        for (int t = 0; t < 16; t++) o[t] += __shfl_xor_sync(0xffffffffu, o[t], off);
    if (lane < 16)
        out[(size_t)i * 16 + lane] = o[lane] + sb2[lane] + x[(size_t)i * 16 + lane];
}

// ---------------- CSR build ----------------
__global__ void k_hist(const int* __restrict__ ei) {
    int e = blockIdx.x * blockDim.x + threadIdx.x;
    if (e >= EE) return;
    int s = ei[e], d = ei[EE + e];
    atomicAdd(&g_deg[d], 1);
    atomicAdd(&g_deg[s], 1);
}

__global__ void k_scan() {  // single block, 1024 threads; also zeroes g_cnt, fills degf/dis
    __shared__ int part[1024];
    const int CH = (NN + 1023) / 1024;  // 20
    int t = threadIdx.x;
    int base = t * CH;
    int s = 0;
    for (int j = 0; j < CH; j++) {
        int idx = base + j;
        if (idx < NN) s += g_deg[idx];
    }
    part[t] = s;
    __syncthreads();
    for (int off = 1; off < 1024; off <<= 1) {
        int v = (t >= off) ? part[t - off] : 0;
        __syncthreads();
        part[t] += v;
        __syncthreads();
    }
    int run = (t > 0) ? part[t - 1] : 0;
    for (int j = 0; j < CH; j++) {
        int idx = base + j;
        if (idx < NN) {
            g_off[idx] = run;
            int d = g_deg[idx];
            run += d;
            g_cnt[idx] = 0;
            g_degf[idx] = (float)d;
            g_dis[idx]  = (d > 0) ? rsqrtf((float)d) : 0.0f;
        }
    }
    if (t == 1023) g_off[NN] = run;
}

__global__ void k_fill(const int* __restrict__ ei) {
    int e = blockIdx.x * blockDim.x + threadIdx.x;
    if (e >= EE) return;
    int s0 = ei[e], d0 = ei[EE + e];
    int p = atomicAdd(&g_cnt[d0], 1);
    int slot = g_off[d0] + p;
    g_csr_src[slot] = s0;
    g_csr_rid[slot] = e;
    p = atomicAdd(&g_cnt[s0], 1);
    slot = g_off[s0] + p;
    g_csr_src[slot] = d0;
    g_csr_rid[slot] = e;
}

// ---------------- 3xTF32 tensor-core GEMM, 64x64 tile ----------------
// D[M,N] = A[M,K] @ B[K,N] (+Cin)(+rowscale*bias)(relu).
// Split hi/lo at smem-store time; inner loop: acc += al*bh + ah*bl + ah*bh.
// grid.z batches over (B += z*bStride, D += z*dStride).
__global__ __launch_bounds__(128)
void k_gemm_tc(const float* __restrict__ A, int lda,
               const float* __restrict__ B, long bStride,
               float* __restrict__ D, int ldd, long dStride,
               const float* __restrict__ Cin, int ldc,
               const float* __restrict__ bias, const float* __restrict__ rowscale,
               int M, int K, int N, int relu) {
    using namespace nvcuda;
    __shared__ float Ah[2][64 * 20], Al[2][64 * 20];
    __shared__ float Bh[2][16 * 72], Bl[2][16 * 72];

    B += (size_t)blockIdx.z * bStride;
    D += (size_t)blockIdx.z * dStride;

    int tid = threadIdx.x;
    int wid = tid >> 5, lane = tid & 31;
    int wm = wid >> 1, wn = wid & 1;
    int row0 = blockIdx.y * 64, col0 = blockIdx.x * 64;

    wmma::fragment<wmma::accumulator, 16, 16, 8, float> acc[2][2];
#pragma unroll
    for (int mi = 0; mi < 2; mi++)
#pragma unroll
        for (int ni = 0; ni < 2; ni++) wmma::fill_fragment(acc[mi][ni], 0.0f);

    int KT = K >> 4;

    auto split = [](float v, float& hi, float& lo) {
        hi = wmma::__float_to_tf32(v);
        lo = wmma::__float_to_tf32(v - hi);
    };
    auto loadA = [&](int kt, int buf) {
        int k0 = kt << 4;
#pragma unroll
        for (int i = 0; i < 2; i++) {
            int v = tid + (i << 7);
            int r = v >> 2, c = (v & 3) << 2;
            int gr = row0 + r;
            float4 a = make_float4(0.f, 0.f, 0.f, 0.f);
            if (gr < M) a = *(const float4*)(A + (size_t)gr * lda + k0 + c);
            float4 h, l;
            split(a.x, h.x, l.x); split(a.y, h.y, l.y);
            split(a.z, h.z, l.z); split(a.w, h.w, l.w);
            *(float4*)&Ah[buf][r * 20 + c] = h;
            *(float4*)&Al[buf][r * 20 + c] = l;
        }
    };
    auto loadB = [&](int kt, int buf) {
        int k0 = kt << 4;
#pragma unroll
        for (int i = 0; i < 2; i++) {
            int v = tid + (i << 7);
            int r = v >> 4, c = (v & 15) << 2;
            int gc = col0 + c;
            float4 b = make_float4(0.f, 0.f, 0.f, 0.f);
            if (gc < N) b = *(const float4*)(B + (size_t)(k0 + r) * N + gc);
            float4 h, l;
            split(b.x, h.x, l.x); split(b.y, h.y, l.y);
            split(b.z, h.z, l.z); split(b.w, h.w, l.w);
            *(float4*)&Bh[buf][r * 72 + c] = h;
            *(float4*)&Bl[buf][r * 72 + c] = l;
        }
    };

    loadA(0, 0); loadB(0, 0);
    __syncthreads();
    for (int kt = 0; kt < KT; kt++) {
        int buf = kt & 1;
        if (kt + 1 < KT) { loadA(kt + 1, buf ^ 1); loadB(kt + 1, buf ^ 1); }
#pragma unroll
        for (int ks = 0; ks < 2; ks++) {
            wmma::fragment<wmma::matrix_a, 16, 16, 8, wmma::precision::tf32, wmma::row_major> ah[2], al[2];
            wmma::fragment<wmma::matrix_b, 16, 16, 8, wmma::precision::tf32, wmma::row_major> bh[2], bl[2];
#pragma unroll
            for (int mi = 0; mi < 2; mi++) {
                wmma::load_matrix_sync(ah[mi], &Ah[buf][(wm * 32 + mi * 16) * 20 + ks * 8], 20);
                wmma::load_matrix_sync(al[mi], &Al[buf][(wm * 32 + mi * 16) * 20 + ks * 8], 20);
            }
#pragma unroll
            for (int ni = 0; ni < 2; ni++) {
                wmma::load_matrix_sync(bh[ni], &Bh[buf][(ks * 8) * 72 + wn * 32 + ni * 16], 72);
                wmma::load_matrix_sync(bl[ni], &Bl[buf][(ks * 8) * 72 + wn * 32 + ni * 16], 72);
            }
#pragma unroll
            for (int mi = 0; mi < 2; mi++)
#pragma unroll
                for (int ni = 0; ni < 2; ni++) {
                    wmma::mma_sync(acc[mi][ni], al[mi], bh[ni], acc[mi][ni]);
                    wmma::mma_sync(acc[mi][ni], ah[mi], bl[ni], acc[mi][ni]);
                    wmma::mma_sync(acc[mi][ni], ah[mi], bh[ni], acc[mi][ni]);
                }
        }
        __syncthreads();
    }

    // epilogue: per-warp staging in Ah[0]
    float* epi = &Ah[0][0] + wid * 320;
#pragma unroll
    for (int mi = 0; mi < 2; mi++) {
#pragma unroll
        for (int ni = 0; ni < 2; ni++) {
            wmma::store_matrix_sync(epi, acc[mi][ni], 20, wmma::mem_row_major);
            __syncwarp();
            int r = lane >> 1, cb = (lane & 1) * 8;
            int m = row0 + wm * 32 + mi * 16 + r;
            int n0 = col0 + wn * 32 + ni * 16 + cb;
            if (m < M && n0 < N) {
                float rs = rowscale ? rowscale[m] : 1.0f;
                float4 v0 = *(float4*)&epi[r * 20 + cb];
                float4 v1 = *(float4*)&epi[r * 20 + cb + 4];
                if (Cin) {
                    float4 c0 = *(const float4*)(Cin + (size_t)m * ldc + n0);
                    float4 c1 = *(const float4*)(Cin + (size_t)m * ldc + n0 + 4);
                    v0.x += c0.x; v0.y += c0.y; v0.z += c0.z; v0.w += c0.w;
                    v1.x += c1.x; v1.y += c1.y; v1.z += c1.z; v1.w += c1.w;
                }
                if (bias) {
                    float4 b0 = *(const float4*)(bias + n0);
                    float4 b1 = *(const float4*)(bias + n0 + 4);
                    v0.x += rs * b0.x; v0.y += rs * b0.y; v0.z += rs * b0.z; v0.w += rs * b0.w;
                    v1.x += rs * b1.x; v1.y += rs * b1.y; v1.z += rs * b1.z; v1.w += rs * b1.w;
                }
                if (relu) {
                    v0.x = fmaxf(v0.x, 0.f); v0.y = fmaxf(v0.y, 0.f);
                    v0.z = fmaxf(v0.z, 0.f); v0.w = fmaxf(v0.w, 0.f);
                    v1.x = fmaxf(v1.x, 0.f); v1.y = fmaxf(v1.y, 0.f);
                    v1.z = fmaxf(v1.z, 0.f); v1.w = fmaxf(v1.w, 0.f);
                }
                *(float4*)(D + (size_t)m * ldd + n0)     = v0;
                *(float4*)(D + (size_t)m * ldd + n0 + 4) = v1;
            }
            __syncwarp();
        }
    }
}

// ---------------- fused EA edge pass ----------------
// S[i] = sum_neighbors relu( P[i] + Q[src] + (ea[rid] @ W1e + b1) )
__global__ __launch_bounds__(256)
void k_edge_f(const float* __restrict__ P, const float* __restrict__ Q,
              const float* __restrict__ EA, const float* __restrict__ W1e,
              const float* __restrict__ b1, float* __restrict__ S) {
    __shared__ float sw[16 * 128];
    __shared__ float sb[128];
    for (int v = threadIdx.x; v < 2048; v += blockDim.x) sw[v] = W1e[v];
    for (int v = threadIdx.x; v < 128; v += blockDim.x) sb[v] = b1[v];
    __syncthreads();
    int lane = threadIdx.x & 31;
    int f = lane * 4;
    float w[16][4];
#pragma unroll
    for (int k = 0; k < 16; k++) {
        float4 t = *(const float4*)&sw[k * 128 + f];
        w[k][0] = t.x; w[k][1] = t.y; w[k][2] = t.z; w[k][3] = t.w;
    }
    float4 bb = *(const float4*)&sb[f];

    int i = (blockIdx.x * blockDim.x + threadIdx.x) >> 5;
    if (i >= NN) return;
    float4 p = *(const float4*)(P + (size_t)i * HD + f);
    float4 acc = make_float4(0.f, 0.f, 0.f, 0.f);
    int s1 = g_off[i + 1];
    for (int s = g_off[i]; s < s1; s++) {
        int src = g_csr_src[s];
        int rid = g_csr_rid[s];
        float val = (lane < 16) ? EA[(size_t)rid * 16 + lane] : 0.0f;
        float4 q = *(const float4*)(Q + (size_t)src * HD + f);
        float4 r = bb;
#pragma unroll
        for (int k = 0; k < 16; k++) {
            float a = __shfl_sync(0xffffffffu, val, k);
            r.x += a * w[k][0]; r.y += a * w[k][1];
            r.z += a * w[k][2]; r.w += a * w[k][3];
        }
        acc.x += fmaxf(p.x + q.x + r.x, 0.f);
        acc.y += fmaxf(p.y + q.y + r.y, 0.f);
        acc.z += fmaxf(p.z + q.z + r.z, 0.f);
        acc.w += fmaxf(p.w + q.w + r.w, 0.f);
    }
    *(float4*)(S + (size_t)i * HD + f) = acc;
}

// ---------------- TAG propagation (norm folded via dis) ----------------
// Xn[i] = dis[i] * sum_neighbors dis[src] * Xc[src]      (ld = 512)
__global__ __launch_bounds__(256)
void k_prop(const float* __restrict__ Xc, float* __restrict__ Xn) {
    int i = (blockIdx.x * blockDim.x + threadIdx.x) >> 5;
    if (i >= NN) return;
    int lane = threadIdx.x & 31;
    int f = lane * 4;
    float4 acc = make_float4(0.f, 0.f, 0.f, 0.f);
    int s1 = g_off[i + 1];
    for (int s = g_off[i]; s < s1; s++) {
        int src = g_csr_src[s];
        float nm = __ldg(&g_dis[src]);
        float4 h = *(const float4*)(Xc + (size_t)src * 512 + f);
        acc.x += nm * h.x; acc.y += nm * h.y;
        acc.z += nm * h.z; acc.w += nm * h.w;
    }
    float di = __ldg(&g_dis[i]);
    acc.x *= di; acc.y *= di; acc.z *= di; acc.w *= di;
    *(float4*)(Xn + (size_t)i * 512 + f) = acc;
}

// ---------------- host ----------------
static void gemm(const float* A, int lda, const float* B, long bStride,
                 float* D, int ldd, long dStride,
                 const float* Cin, int ldc, const float* bias, const float* rowscale,
                 int M, int K, int N, int relu, int batch) {
    dim3 grid((N + 63) / 64, (M + 63) / 64, batch);
    k_gemm_tc<<<grid, 128>>>(A, lda, B, bStride, D, ldd, dStride,
                             Cin, ldc, bias, rowscale, M, K, N, relu);
}

extern "C" void kernel_launch(void* const* d_in, const int* in_sizes, int n_in,
                              void* d_out, int out_size) {
    const float* x         = (const float*)d_in[0];
    const float* mask      = (const float*)d_in[1];
    const float* edge_attr = (const float*)d_in[2];
    const int* edge_index;
    int base;
    if (in_sizes[3] == 2 * EE) {           // setup_inputs dict order
        edge_index = (const int*)d_in[3];
        base = 4;
    } else {                               // reference-signature order (edge_index last)
        edge_index = (const int*)d_in[n_in - 1];
        base = 3;
    }
    const float* m_w1   = (const float*)d_in[base + 0];
    const float* m_b1   = (const float*)d_in[base + 1];
    const float* m_w2   = (const float*)d_in[base + 2];
    const float* m_b2   = (const float*)d_in[base + 3];
    const float* ea0_w1 = (const float*)d_in[base + 4];
    const float* ea0_b1 = (const float*)d_in[base + 5];
    const float* ea0_w2 = (const float*)d_in[base + 6];
    const float* ea0_b2 = (const float*)d_in[base + 7];
    const float* tag0_w = (const float*)d_in[base + 8];
    const float* tag0_b = (const float*)d_in[base + 9];
    const float* ea1_w1 = (const float*)d_in[base + 10];
    const float* ea1_b1 = (const float*)d_in[base + 11];
    const float* ea1_w2 = (const float*)d_in[base + 12];
    const float* ea1_b2 = (const float*)d_in[base + 13];
    const float* tag1_w = (const float*)d_in[base + 14];
    const float* tag1_b = (const float*)d_in[base + 15];
    const float* ea2_w1 = (const float*)d_in[base + 16];
    const float* ea2_b1 = (const float*)d_in[base + 17];
    const float* ea2_w2 = (const float*)d_in[base + 18];
    const float* ea2_b2 = (const float*)d_in[base + 19];

    float *pAB, *pC, *pH, *pX, *ph16, *pdegf;
    cudaGetSymbolAddress((void**)&pAB, g_AB);
    cudaGetSymbolAddress((void**)&pC, g_C);
    cudaGetSymbolAddress((void**)&pH, g_H);
    cudaGetSymbolAddress((void**)&pX, g_X);
    cudaGetSymbolAddress((void**)&ph16, g_h16);
    cudaGetSymbolAddress((void**)&pdegf, g_degf);
    float* pA = pAB;
    float* pB = pAB + (size_t)NN * HD;

    const int EB = 2500;              // 20000 node-warps / 8 warps per block
    const long NSTR = (long)NN * HD;  // batch stride for projections

    // launches 0-3: mask MLP (+deg zeroing), CSR build
    k_mask<<<EB, 256>>>(mask, x, m_w1, m_b1, m_w2, m_b2, ph16);
    k_hist<<<(EE + 255) / 256, 256>>>(edge_index);
    k_scan<<<1, 1024>>>();
    k_fill<<<(EE + 255) / 256, 256>>>(edge_index);

    // ---- EA0 (in=16) ----
    gemm(ph16, 16, ea0_w1, 16 * 128, pAB, 128, NSTR, nullptr, 0, nullptr, nullptr,
         NN, 16, 128, 0, 2);                                        // launch 4
    k_edge_f<<<EB, 256>>>(pA, pB, edge_attr, ea0_w1 + 32 * 128, ea0_b1, pC);  // launch 5 (ncu)
    gemm(pC, 128, ea0_w2, 0, pX, 512, 0, nullptr, 0, ea0_b2, pdegf, NN, 128, 128, 1, 1);

    // ---- TAG0: props fill X slices, one K=512 GEMM ----
    k_prop<<<EB, 256>>>(pX,       pX + 128);
    k_prop<<<EB, 256>>>(pX + 128, pX + 256);
    k_prop<<<EB, 256>>>(pX + 256, pX + 384);
    gemm(pX, 512, tag0_w, 0, pH, 128, 0, nullptr, 0, tag0_b, nullptr, NN, 512, 128, 1, 1);

    // ---- EA1 (in=128) ----
    gemm(pH, 128, ea1_w1, 128 * 128, pAB, 128, NSTR, nullptr, 0, nullptr, nullptr,
         NN, 128, 128, 0, 2);
    k_edge_f<<<EB, 256>>>(pA, pB, edge_attr, ea1_w1 + 256 * 128, ea1_b1, pC);
    gemm(pC, 128, ea1_w2, 0, pX, 512, 0, nullptr, 0, ea1_b2, pdegf, NN, 128, 128, 1, 1);

    // ---- TAG1 ----
    k_prop<<<EB, 256>>>(pX,       pX + 128);
    k_prop<<<EB, 256>>>(pX + 128, pX + 256);
    k_prop<<<EB, 256>>>(pX + 256, pX + 384);
    gemm(pX, 512, tag1_w, 0, pH, 128, 0, nullptr, 0, tag1_b, nullptr, NN, 512, 128, 1, 1);

    // ---- EA2 (final, no relu, out = [N,16]) ----
    gemm(pH, 128, ea2_w1, 128 * 128, pAB, 128, NSTR, nullptr, 0, nullptr, nullptr,
         NN, 128, 128, 0, 2);
    k_edge_f<<<EB, 256>>>(pA, pB, edge_attr, ea2_w1 + 256 * 128, ea2_b1, pC);
    gemm(pC, 128, ea2_w2, 0, (float*)d_out, 16, 0, nullptr, 0, ea2_b2, pdegf,
         NN, 128, 16, 0, 1);
}

// round 8
// speedup vs baseline: 1.2652x; 1.2600x over previous
#include <cuda_runtime.h>
#include <cuda_bf16.h>
#include <mma.h>
#include <cstdint>

#define NN 20000
#define EE 160000
#define E2 320000
#define HD 128

// ---------------- static scratch (no allocations allowed) ----------------
static __device__ float g_AB[2 * NN * HD];       // P | Q projections (contiguous for grid.z)
static __device__ float g_C[NN * HD];
static __device__ float g_H[NN * HD];
static __device__ float g_X[(size_t)NN * 512];   // [h | Lh | L^2h | L^3h]
static __device__ float g_h16[NN * 16];
static __device__ float g_degf[NN];
static __device__ float g_dis[NN];
static __device__ int   g_deg[NN];
static __device__ int   g_cnt[NN];
static __device__ int   g_off[NN + 1];
static __device__ int   g_csr_src[E2];
static __device__ int   g_csr_rid[E2];

// ---------------- fused mask MLP (+ zero g_deg) ----------------
__global__ __launch_bounds__(256)
void k_mask(const float* __restrict__ mask, const float* __restrict__ x,
            const float* __restrict__ w1, const float* __restrict__ b1,
            const float* __restrict__ w2, const float* __restrict__ b2,
            float* __restrict__ out) {
    __shared__ float sw1[16 * 128];
    __shared__ float sb1[128];
    __shared__ float sw2[128 * 16];
    __shared__ float sb2[16];
    for (int v = threadIdx.x; v < 2048; v += blockDim.x) { sw1[v] = w1[v]; sw2[v] = w2[v]; }
    for (int v = threadIdx.x; v < 128; v += blockDim.x) sb1[v] = b1[v];
    if (threadIdx.x < 16) sb2[threadIdx.x] = b2[threadIdx.x];

    int gt = blockIdx.x * blockDim.x + threadIdx.x;
    if (gt < NN) g_deg[gt] = 0;
    __syncthreads();

    int i = gt >> 5;
    if (i >= NN) return;
    int lane = threadIdx.x & 31;
    int f = lane * 4;
    float m = (lane < 16) ? mask[(size_t)i * 16 + lane] : 0.0f;
    float4 h = *(const float4*)&sb1[f];
#pragma unroll
    for (int k = 0; k < 16; k++) {
        float a = __shfl_sync(0xffffffffu, m, k);
        const float4 w = *(const float4*)&sw1[k * 128 + f];
        h.x += a * w.x; h.y += a * w.y; h.z += a * w.z; h.w += a * w.w;
    }
    h.x = fmaxf(h.x, 0.f); h.y = fmaxf(h.y, 0.f);
    h.z = fmaxf(h.z, 0.f); h.w = fmaxf(h.w, 0.f);

    float o[16];
#pragma unroll
    for (int t = 0; t < 16; t++) o[t] = 0.0f;
    float hv[4] = {h.x, h.y, h.z, h.w};
#pragma unroll
    for (int j = 0; j < 4; j++) {
        const float* wrow = &sw2[(f + j) * 16];
        float hj = hv[j];
#pragma unroll
        for (int t = 0; t < 16; t++) o[t] += hj * wrow[t];
    }
#pragma unroll
    for (int off = 16; off > 0; off >>= 1)
#pragma unroll
        for (int t = 0; t < 16; t++) o[t] += __shfl_xor_sync(0xffffffffu, o[t], off);
    if (lane < 16)
        out[(size_t)i * 16 + lane] = o[lane] + sb2[lane] + x[(size_t)i * 16 + lane];
}

// ---------------- CSR build ----------------
__global__ void k_hist(const int* __restrict__ ei) {
    int e = blockIdx.x * blockDim.x + threadIdx.x;
    if (e >= EE) return;
    int s = ei[e], d = ei[EE + e];
    atomicAdd(&g_deg[d], 1);
    atomicAdd(&g_deg[s], 1);
}

__global__ void k_scan() {
    __shared__ int part[1024];
    const int CH = (NN + 1023) / 1024;
    int t = threadIdx.x;
    int base = t * CH;
    int s = 0;
    for (int j = 0; j < CH; j++) {
        int idx = base + j;
        if (idx < NN) s += g_deg[idx];
    }
    part[t] = s;
    __syncthreads();
    for (int off = 1; off < 1024; off <<= 1) {
        int v = (t >= off) ? part[t - off] : 0;
        __syncthreads();
        part[t] += v;
        __syncthreads();
    }
    int run = (t > 0) ? part[t - 1] : 0;
    for (int j = 0; j < CH; j++) {
        int idx = base + j;
        if (idx < NN) {
            g_off[idx] = run;
            int d = g_deg[idx];
            run += d;
            g_cnt[idx] = 0;
            g_degf[idx] = (float)d;
            g_dis[idx]  = (d > 0) ? rsqrtf((float)d) : 0.0f;
        }
    }
    if (t == 1023) g_off[NN] = run;
}

__global__ void k_fill(const int* __restrict__ ei) {
    int e = blockIdx.x * blockDim.x + threadIdx.x;
    if (e >= EE) return;
    int s0 = ei[e], d0 = ei[EE + e];
    int p = atomicAdd(&g_cnt[d0], 1);
    int slot = g_off[d0] + p;
    g_csr_src[slot] = s0;
    g_csr_rid[slot] = e;
    p = atomicAdd(&g_cnt[s0], 1);
    slot = g_off[s0] + p;
    g_csr_src[slot] = d0;
    g_csr_rid[slot] = e;
}

// ---------------- bf16x3 tensor-core GEMM ----------------
// D[M,N] = A[M,K]@B[K,N] (+Cin)(+rowscale*bias)(relu), emulated fp32 via
// bf16 hi/mid split: acc += am*bh + ah*bm + ah*bh (am*bm ~2^-16 dropped).
// CTA tile 64x128, 4 warps (2m x 2n), warp tile 32x64, BK=32 double-buffered.
__device__ __forceinline__ void split4(float4 a, __nv_bfloat16* ph, __nv_bfloat16* pm) {
    __nv_bfloat162 h0 = __floats2bfloat162_rn(a.x, a.y);
    __nv_bfloat162 h1 = __floats2bfloat162_rn(a.z, a.w);
    __nv_bfloat162 m0 = __floats2bfloat162_rn(a.x - __bfloat162float(h0.x),
                                              a.y - __bfloat162float(h0.y));
    __nv_bfloat162 m1 = __floats2bfloat162_rn(a.z - __bfloat162float(h1.x),
                                              a.w - __bfloat162float(h1.y));
    *(__nv_bfloat162*)ph = h0; *(__nv_bfloat162*)(ph + 2) = h1;
    *(__nv_bfloat162*)pm = m0; *(__nv_bfloat162*)(pm + 2) = m1;
}

#define GEMM_SMEM 55296
// layout in halves: Ah[2][2560] (ld 40), Am[2][2560], Bh[2][4352] (ld 136), Bm[2][4352]

__global__ __launch_bounds__(128)
void k_gemm_tc(const float* __restrict__ A, int lda,
               const float* __restrict__ B, long bStride,
               float* __restrict__ D, int ldd, long dStride,
               const float* __restrict__ Cin, int ldc,
               const float* __restrict__ bias, const float* __restrict__ rowscale,
               int M, int K, int N, int relu) {
    using namespace nvcuda;
    extern __shared__ char sm_raw[];
    __nv_bfloat16* Ah = (__nv_bfloat16*)sm_raw;
    __nv_bfloat16* Am = Ah + 2 * 2560;
    __nv_bfloat16* Bh = Am + 2 * 2560;
    __nv_bfloat16* Bm = Bh + 2 * 4352;

    B += (size_t)blockIdx.z * bStride;
    D += (size_t)blockIdx.z * dStride;

    int tid = threadIdx.x;
    int wid = tid >> 5, lane = tid & 31;
    int wm = wid >> 1, wn = wid & 1;
    int row0 = blockIdx.y * 64, col0 = blockIdx.x * 128;

    wmma::fragment<wmma::accumulator, 16, 16, 16, float> acc[2][4];
#pragma unroll
    for (int mi = 0; mi < 2; mi++)
#pragma unroll
        for (int ni = 0; ni < 4; ni++) wmma::fill_fragment(acc[mi][ni], 0.0f);

    int KT = (K + 31) >> 5;

    auto loadA = [&](int kt, int buf) {
        int k0 = kt << 5;
#pragma unroll
        for (int i = 0; i < 4; i++) {
            int v = tid + (i << 7);             // 0..511
            int r = v >> 3, c = (v & 7) << 2;
            int gr = row0 + r;
            float4 a = make_float4(0.f, 0.f, 0.f, 0.f);
            if (gr < M && k0 + c < K) a = *(const float4*)(A + (size_t)gr * lda + k0 + c);
            int idx = buf * 2560 + r * 40 + c;
            split4(a, &Ah[idx], &Am[idx]);
        }
    };
    auto loadB = [&](int kt, int buf) {
        int k0 = kt << 5;
#pragma unroll
        for (int i = 0; i < 8; i++) {
            int v = tid + (i << 7);             // 0..1023
            int r = v >> 5, c = (v & 31) << 2;
            int gc = col0 + c;
            float4 b = make_float4(0.f, 0.f, 0.f, 0.f);
            if (gc < N && k0 + r < K) b = *(const float4*)(B + (size_t)(k0 + r) * N + gc);
            int idx = buf * 4352 + r * 136 + c;
            split4(b, &Bh[idx], &Bm[idx]);
        }
    };

    loadA(0, 0); loadB(0, 0);
    __syncthreads();
    for (int kt = 0; kt < KT; kt++) {
        int buf = kt & 1;
        if (kt + 1 < KT) { loadA(kt + 1, buf ^ 1); loadB(kt + 1, buf ^ 1); }
#pragma unroll
        for (int ks = 0; ks < 2; ks++) {
            wmma::fragment<wmma::matrix_a, 16, 16, 16, __nv_bfloat16, wmma::row_major> ah[2], am[2];
            wmma::fragment<wmma::matrix_b, 16, 16, 16, __nv_bfloat16, wmma::row_major> bh[4], bm[4];
#pragma unroll
            for (int mi = 0; mi < 2; mi++) {
                int off = buf * 2560 + (wm * 32 + mi * 16) * 40 + ks * 16;
                wmma::load_matrix_sync(ah[mi], &Ah[off], 40);
                wmma::load_matrix_sync(am[mi], &Am[off], 40);
            }
#pragma unroll
            for (int ni = 0; ni < 4; ni++) {
                int off = buf * 4352 + (ks * 16) * 136 + wn * 64 + ni * 16;
                wmma::load_matrix_sync(bh[ni], &Bh[off], 136);
                wmma::load_matrix_sync(bm[ni], &Bm[off], 136);
            }
#pragma unroll
            for (int mi = 0; mi < 2; mi++)
#pragma unroll
                for (int ni = 0; ni < 4; ni++) {
                    wmma::mma_sync(acc[mi][ni], am[mi], bh[ni], acc[mi][ni]);
                    wmma::mma_sync(acc[mi][ni], ah[mi], bm[ni], acc[mi][ni]);
                    wmma::mma_sync(acc[mi][ni], ah[mi], bh[ni], acc[mi][ni]);
                }
        }
        __syncthreads();
    }

    // epilogue: reuse smem front as float staging (4 warps x 320 floats)
    float* epi = (float*)sm_raw + wid * 320;
#pragma unroll
    for (int mi = 0; mi < 2; mi++) {
#pragma unroll
        for (int ni = 0; ni < 4; ni++) {
            wmma::store_matrix_sync(epi, acc[mi][ni], 20, wmma::mem_row_major);
            __syncwarp();
            int r = lane >> 1, cb = (lane & 1) * 8;
            int m = row0 + wm * 32 + mi * 16 + r;
            int n0 = col0 + wn * 64 + ni * 16 + cb;
            if (m < M && n0 < N) {
                float rs = rowscale ? rowscale[m] : 1.0f;
                float4 v0 = *(float4*)&epi[r * 20 + cb];
                float4 v1 = *(float4*)&epi[r * 20 + cb + 4];
                if (Cin) {
                    float4 c0 = *(const float4*)(Cin + (size_t)m * ldc + n0);
                    float4 c1 = *(const float4*)(Cin + (size_t)m * ldc + n0 + 4);
                    v0.x += c0.x; v0.y += c0.y; v0.z += c0.z; v0.w += c0.w;
                    v1.x += c1.x; v1.y += c1.y; v1.z += c1.z; v1.w += c1.w;
                }
                if (bias) {
                    float4 b0 = *(const float4*)(bias + n0);
                    float4 b1 = *(const float4*)(bias + n0 + 4);
                    v0.x += rs * b0.x; v0.y += rs * b0.y; v0.z += rs * b0.z; v0.w += rs * b0.w;
                    v1.x += rs * b1.x; v1.y += rs * b1.y; v1.z += rs * b1.z; v1.w += rs * b1.w;
                }
                if (relu) {
                    v0.x = fmaxf(v0.x, 0.f); v0.y = fmaxf(v0.y, 0.f);
                    v0.z = fmaxf(v0.z, 0.f); v0.w = fmaxf(v0.w, 0.f);
                    v1.x = fmaxf(v1.x, 0.f); v1.y = fmaxf(v1.y, 0.f);
                    v1.z = fmaxf(v1.z, 0.f); v1.w = fmaxf(v1.w, 0.f);
                }
                *(float4*)(D + (size_t)m * ldd + n0)     = v0;
                *(float4*)(D + (size_t)m * ldd + n0 + 4) = v1;
            }
            __syncwarp();
        }
    }
}

// ---------------- fused EA edge pass ----------------
__global__ __launch_bounds__(256)
void k_edge_f(const float* __restrict__ P, const float* __restrict__ Q,
              const float* __restrict__ EA, const float* __restrict__ W1e,
              const float* __restrict__ b1, float* __restrict__ S) {
    __shared__ float sw[16 * 128];
    __shared__ float sb[128];
    for (int v = threadIdx.x; v < 2048; v += blockDim.x) sw[v] = W1e[v];
    for (int v = threadIdx.x; v < 128; v += blockDim.x) sb[v] = b1[v];
    __syncthreads();
    int lane = threadIdx.x & 31;
    int f = lane * 4;
    float w[16][4];
#pragma unroll
    for (int k = 0; k < 16; k++) {
        float4 t = *(const float4*)&sw[k * 128 + f];
        w[k][0] = t.x; w[k][1] = t.y; w[k][2] = t.z; w[k][3] = t.w;
    }
    float4 bb = *(const float4*)&sb[f];

    int i = (blockIdx.x * blockDim.x + threadIdx.x) >> 5;
    if (i >= NN) return;
    float4 p = *(const float4*)(P + (size_t)i * HD + f);
    float4 acc = make_float4(0.f, 0.f, 0.f, 0.f);
    int s1 = g_off[i + 1];
    for (int s = g_off[i]; s < s1; s++) {
        int src = g_csr_src[s];
        int rid = g_csr_rid[s];
        float val = (lane < 16) ? EA[(size_t)rid * 16 + lane] : 0.0f;
        float4 q = *(const float4*)(Q + (size_t)src * HD + f);
        float4 r = bb;
#pragma unroll
        for (int k = 0; k < 16; k++) {
            float a = __shfl_sync(0xffffffffu, val, k);
            r.x += a * w[k][0]; r.y += a * w[k][1];
            r.z += a * w[k][2]; r.w += a * w[k][3];
        }
        acc.x += fmaxf(p.x + q.x + r.x, 0.f);
        acc.y += fmaxf(p.y + q.y + r.y, 0.f);
        acc.z += fmaxf(p.z + q.z + r.z, 0.f);
        acc.w += fmaxf(p.w + q.w + r.w, 0.f);
    }
    *(float4*)(S + (size_t)i * HD + f) = acc;
}

// ---------------- TAG propagation (norm folded via dis), ld = 512 ----------------
__global__ __launch_bounds__(256)
void k_prop(const float* __restrict__ Xc, float* __restrict__ Xn) {
    int i = (blockIdx.x * blockDim.x + threadIdx.x) >> 5;
    if (i >= NN) return;
    int lane = threadIdx.x & 31;
    int f = lane * 4;
    float4 acc = make_float4(0.f, 0.f, 0.f, 0.f);
    int s1 = g_off[i + 1];
    for (int s = g_off[i]; s < s1; s++) {
        int src = g_csr_src[s];
        float nm = __ldg(&g_dis[src]);
        float4 h = *(const float4*)(Xc + (size_t)src * 512 + f);
        acc.x += nm * h.x; acc.y += nm * h.y;
        acc.z += nm * h.z; acc.w += nm * h.w;
    }
    float di = __ldg(&g_dis[i]);
    acc.x *= di; acc.y *= di; acc.z *= di; acc.w *= di;
    *(float4*)(Xn + (size_t)i * 512 + f) = acc;
}

// ---------------- final output: out[i] = C[i]@W2 + deg[i]*b2  (N=16) ----------------
__global__ __launch_bounds__(256)
void k_out(const float* __restrict__ C, const float* __restrict__ W2,
           const float* __restrict__ b2, float* __restrict__ out) {
    __shared__ float sw[128 * 16];
    __shared__ float sb[16];
    for (int v = threadIdx.x; v < 2048; v += blockDim.x) sw[v] = W2[v];
    if (threadIdx.x < 16) sb[threadIdx.x] = b2[threadIdx.x];
    __syncthreads();
    int gt = blockIdx.x * blockDim.x + threadIdx.x;
    int i = gt >> 5;
    if (i >= NN) return;
    int lane = threadIdx.x & 31, f = lane * 4;
    float4 c = *(const float4*)(C + (size_t)i * HD + f);
    float o[16];
#pragma unroll
    for (int t = 0; t < 16; t++) o[t] = 0.0f;
    float cv[4] = {c.x, c.y, c.z, c.w};
#pragma unroll
    for (int j = 0; j < 4; j++) {
        const float* wr = &sw[(f + j) * 16];
        float cj = cv[j];
#pragma unroll
        for (int t = 0; t < 16; t++) o[t] += cj * wr[t];
    }
#pragma unroll
    for (int off = 16; off > 0; off >>= 1)
#pragma unroll
        for (int t = 0; t < 16; t++) o[t] += __shfl_xor_sync(0xffffffffu, o[t], off);
    if (lane < 16)
        out[(size_t)i * 16 + lane] = o[lane] + g_degf[i] * sb[lane];
}

// ---------------- host ----------------
static void gemm(const float* A, int lda, const float* B, long bStride,
                 float* D, int ldd, long dStride,
                 const float* Cin, int ldc, const float* bias, const float* rowscale,
                 int M, int K, int N, int relu, int batch) {
    dim3 grid((N + 127) / 128, (M + 63) / 64, batch);
    k_gemm_tc<<<grid, 128, GEMM_SMEM>>>(A, lda, B, bStride, D, ldd, dStride,
                                        Cin, ldc, bias, rowscale, M, K, N, relu);
}

extern "C" void kernel_launch(void* const* d_in, const int* in_sizes, int n_in,
                              void* d_out, int out_size) {
    const float* x         = (const float*)d_in[0];
    const float* mask      = (const float*)d_in[1];
    const float* edge_attr = (const float*)d_in[2];
    const int* edge_index;
    int base;
    if (in_sizes[3] == 2 * EE) {
        edge_index = (const int*)d_in[3];
        base = 4;
    } else {
        edge_index = (const int*)d_in[n_in - 1];
        base = 3;
    }
    const float* m_w1   = (const float*)d_in[base + 0];
    const float* m_b1   = (const float*)d_in[base + 1];
    const float* m_w2   = (const float*)d_in[base + 2];
    const float* m_b2   = (const float*)d_in[base + 3];
    const float* ea0_w1 = (const float*)d_in[base + 4];
    const float* ea0_b1 = (const float*)d_in[base + 5];
    const float* ea0_w2 = (const float*)d_in[base + 6];
    const float* ea0_b2 = (const float*)d_in[base + 7];
    const float* tag0_w = (const float*)d_in[base + 8];
    const float* tag0_b = (const float*)d_in[base + 9];
    const float* ea1_w1 = (const float*)d_in[base + 10];
    const float* ea1_b1 = (const float*)d_in[base + 11];
    const float* ea1_w2 = (const float*)d_in[base + 12];
    const float* ea1_b2 = (const float*)d_in[base + 13];
    const float* tag1_w = (const float*)d_in[base + 14];
    const float* tag1_b = (const float*)d_in[base + 15];
    const float* ea2_w1 = (const float*)d_in[base + 16];
    const float* ea2_b1 = (const float*)d_in[base + 17];
    const float* ea2_w2 = (const float*)d_in[base + 18];
    const float* ea2_b2 = (const float*)d_in[base + 19];

    float *pAB, *pC, *pH, *pX, *ph16, *pdegf;
    cudaGetSymbolAddress((void**)&pAB, g_AB);
    cudaGetSymbolAddress((void**)&pC, g_C);
    cudaGetSymbolAddress((void**)&pH, g_H);
    cudaGetSymbolAddress((void**)&pX, g_X);
    cudaGetSymbolAddress((void**)&ph16, g_h16);
    cudaGetSymbolAddress((void**)&pdegf, g_degf);
    float* pA = pAB;
    float* pB = pAB + (size_t)NN * HD;

    static int smem_set = 0;
    if (!smem_set) {
        cudaFuncSetAttribute(k_gemm_tc, cudaFuncAttributeMaxDynamicSharedMemorySize, GEMM_SMEM);
        smem_set = 1;
    }

    const int EB = 2500;              // 20000 node-warps / 8 warps per block
    const long NSTR = (long)NN * HD;

    k_mask<<<EB, 256>>>(mask, x, m_w1, m_b1, m_w2, m_b2, ph16);
    k_hist<<<(EE + 255) / 256, 256>>>(edge_index);
    k_scan<<<1, 1024>>>();
    k_fill<<<(EE + 255) / 256, 256>>>(edge_index);

    // ---- EA0 (in=16) ----
    gemm(ph16, 16, ea0_w1, 16 * 128, pAB, 128, NSTR, nullptr, 0, nullptr, nullptr,
         NN, 16, 128, 0, 2);
    k_edge_f<<<EB, 256>>>(pA, pB, edge_attr, ea0_w1 + 32 * 128, ea0_b1, pC);
    gemm(pC, 128, ea0_w2, 0, pX, 512, 0, nullptr, 0, ea0_b2, pdegf, NN, 128, 128, 1, 1);

    // ---- TAG0 ----
    k_prop<<<EB, 256>>>(pX,       pX + 128);
    k_prop<<<EB, 256>>>(pX + 128, pX + 256);
    k_prop<<<EB, 256>>>(pX + 256, pX + 384);
    gemm(pX, 512, tag0_w, 0, pH, 128, 0, nullptr, 0, tag0_b, nullptr, NN, 512, 128, 1, 1);

    // ---- EA1 (in=128) ----
    gemm(pH, 128, ea1_w1, 128 * 128, pAB, 128, NSTR, nullptr, 0, nullptr, nullptr,
         NN, 128, 128, 0, 2);
    k_edge_f<<<EB, 256>>>(pA, pB, edge_attr, ea1_w1 + 256 * 128, ea1_b1, pC);
    gemm(pC, 128, ea1_w2, 0, pX, 512, 0, nullptr, 0, ea1_b2, pdegf, NN, 128, 128, 1, 1);

    // ---- TAG1 ----
    k_prop<<<EB, 256>>>(pX,       pX + 128);
    k_prop<<<EB, 256>>>(pX + 128, pX + 256);
    k_prop<<<EB, 256>>>(pX + 256, pX + 384);
    gemm(pX, 512, tag1_w, 0, pH, 128, 0, nullptr, 0, tag1_b, nullptr, NN, 512, 128, 1, 1);

    // ---- EA2 (final) ----
    gemm(pH, 128, ea2_w1, 128 * 128, pAB, 128, NSTR, nullptr, 0, nullptr, nullptr,
         NN, 128, 128, 0, 2);
    k_edge_f<<<EB, 256>>>(pA, pB, edge_attr, ea2_w1 + 256 * 128, ea2_b1, pC);
    k_out<<<EB, 256>>>(pC, ea2_w2, ea2_b2, (float*)d_out);
}

// round 9
// speedup vs baseline: 1.3124x; 1.0373x over previous
#include <cuda_runtime.h>
#include <cuda_bf16.h>
#include <mma.h>
#include <cstdint>

#define NN 20000
#define EE 160000
#define E2 320000
#define HD 128

// ---------------- static scratch (no allocations allowed) ----------------
static __device__ float g_AB[2 * NN * HD];       // P | Q projections (contiguous for grid.z)
static __device__ float g_C[NN * HD];
static __device__ float g_H[NN * HD];
static __device__ float g_X[(size_t)NN * 512];   // [h | Lh | L^2h | L^3h]
static __device__ float g_h16[NN * 16];
static __device__ float g_degf[NN];
static __device__ float g_dis[NN];
static __device__ int   g_deg[NN];
static __device__ int   g_cnt[NN];
static __device__ int   g_off[NN + 1];
static __device__ int   g_csr_src[E2];
static __device__ int   g_csr_rid[E2];

// ---------------- fused mask MLP (+ zero g_deg) ----------------
__global__ __launch_bounds__(256)
void k_mask(const float* __restrict__ mask, const float* __restrict__ x,
            const float* __restrict__ w1, const float* __restrict__ b1,
            const float* __restrict__ w2, const float* __restrict__ b2,
            float* __restrict__ out) {
    __shared__ float sw1[16 * 128];
    __shared__ float sb1[128];
    __shared__ float sw2[128 * 16];
    __shared__ float sb2[16];
    for (int v = threadIdx.x; v < 2048; v += blockDim.x) { sw1[v] = w1[v]; sw2[v] = w2[v]; }
    for (int v = threadIdx.x; v < 128; v += blockDim.x) sb1[v] = b1[v];
    if (threadIdx.x < 16) sb2[threadIdx.x] = b2[threadIdx.x];

    int gt = blockIdx.x * blockDim.x + threadIdx.x;
    if (gt < NN) g_deg[gt] = 0;
    __syncthreads();

    int i = gt >> 5;
    if (i >= NN) return;
    int lane = threadIdx.x & 31;
    int f = lane * 4;
    float m = (lane < 16) ? mask[(size_t)i * 16 + lane] : 0.0f;
    float4 h = *(const float4*)&sb1[f];
#pragma unroll
    for (int k = 0; k < 16; k++) {
        float a = __shfl_sync(0xffffffffu, m, k);
        const float4 w = *(const float4*)&sw1[k * 128 + f];
        h.x += a * w.x; h.y += a * w.y; h.z += a * w.z; h.w += a * w.w;
    }
    h.x = fmaxf(h.x, 0.f); h.y = fmaxf(h.y, 0.f);
    h.z = fmaxf(h.z, 0.f); h.w = fmaxf(h.w, 0.f);

    float o[16];
#pragma unroll
    for (int t = 0; t < 16; t++) o[t] = 0.0f;
    float hv[4] = {h.x, h.y, h.z, h.w};
#pragma unroll
    for (int j = 0; j < 4; j++) {
        const float* wrow = &sw2[(f + j) * 16];
        float hj = hv[j];
#pragma unroll
        for (int t = 0; t < 16; t++) o[t] += hj * wrow[t];
    }
#pragma unroll
    for (int off = 16; off > 0; off >>= 1)
#pragma unroll
        for (int t = 0; t < 16; t++) o[t] += __shfl_xor_sync(0xffffffffu, o[t], off);
    if (lane < 16)
        out[(size_t)i * 16 + lane] = o[lane] + sb2[lane] + x[(size_t)i * 16 + lane];
}

// ---------------- CSR build ----------------
__global__ void k_hist(const int* __restrict__ ei) {
    int e = blockIdx.x * blockDim.x + threadIdx.x;
    if (e >= EE) return;
    int s = ei[e], d = ei[EE + e];
    atomicAdd(&g_deg[d], 1);
    atomicAdd(&g_deg[s], 1);
}

__global__ void k_scan() {
    __shared__ int part[1024];
    const int CH = (NN + 1023) / 1024;
    int t = threadIdx.x;
    int base = t * CH;
    int s = 0;
    for (int j = 0; j < CH; j++) {
        int idx = base + j;
        if (idx < NN) s += g_deg[idx];
    }
    part[t] = s;
    __syncthreads();
    for (int off = 1; off < 1024; off <<= 1) {
        int v = (t >= off) ? part[t - off] : 0;
        __syncthreads();
        part[t] += v;
        __syncthreads();
    }
    int run = (t > 0) ? part[t - 1] : 0;
    for (int j = 0; j < CH; j++) {
        int idx = base + j;
        if (idx < NN) {
            g_off[idx] = run;
            int d = g_deg[idx];
            run += d;
            g_cnt[idx] = 0;
            g_degf[idx] = (float)d;
            g_dis[idx]  = (d > 0) ? rsqrtf((float)d) : 0.0f;
        }
    }
    if (t == 1023) g_off[NN] = run;
}

__global__ void k_fill(const int* __restrict__ ei) {
    int e = blockIdx.x * blockDim.x + threadIdx.x;
    if (e >= EE) return;
    int s0 = ei[e], d0 = ei[EE + e];
    int p = atomicAdd(&g_cnt[d0], 1);
    int slot = g_off[d0] + p;
    g_csr_src[slot] = s0;
    g_csr_rid[slot] = e;
    p = atomicAdd(&g_cnt[s0], 1);
    slot = g_off[s0] + p;
    g_csr_src[slot] = d0;
    g_csr_rid[slot] = e;
}

// ---------------- bf16x3 tensor-core GEMM ----------------
// D[M,N] = A[M,K]@B[K,N] (+Cin)(+rowscale*bias)(relu), emulated fp32 via
// bf16 hi/mid split: acc += am*bh + ah*bm + ah*bh (am*bm ~2^-16 dropped).
// CTA tile 64x128, 4 warps (2m x 2n), warp tile 32x64, BK=32 double-buffered.
__device__ __forceinline__ void split4(float4 a, __nv_bfloat16* ph, __nv_bfloat16* pm) {
    __nv_bfloat162 h0 = __floats2bfloat162_rn(a.x, a.y);
    __nv_bfloat162 h1 = __floats2bfloat162_rn(a.z, a.w);
    __nv_bfloat162 m0 = __floats2bfloat162_rn(a.x - __bfloat162float(h0.x),
                                              a.y - __bfloat162float(h0.y));
    __nv_bfloat162 m1 = __floats2bfloat162_rn(a.z - __bfloat162float(h1.x),
                                              a.w - __bfloat162float(h1.y));
    *(__nv_bfloat162*)ph = h0; *(__nv_bfloat162*)(ph + 2) = h1;
    *(__nv_bfloat162*)pm = m0; *(__nv_bfloat162*)(pm + 2) = m1;
}

#define GEMM_SMEM 55296
// layout in halves: Ah[2][2560] (ld 40), Am[2][2560], Bh[2][4352] (ld 136), Bm[2][4352]

__global__ __launch_bounds__(128)
void k_gemm_tc(const float* __restrict__ A, int lda,
               const float* __restrict__ B, long bStride,
               float* __restrict__ D, int ldd, long dStride,
               const float* __restrict__ Cin, int ldc,
               const float* __restrict__ bias, const float* __restrict__ rowscale,
               int M, int K, int N, int relu) {
    using namespace nvcuda;
    extern __shared__ char sm_raw[];
    __nv_bfloat16* Ah = (__nv_bfloat16*)sm_raw;
    __nv_bfloat16* Am = Ah + 2 * 2560;
    __nv_bfloat16* Bh = Am + 2 * 2560;
    __nv_bfloat16* Bm = Bh + 2 * 4352;

    B += (size_t)blockIdx.z * bStride;
    D += (size_t)blockIdx.z * dStride;

    int tid = threadIdx.x;
    int wid = tid >> 5, lane = tid & 31;
    int wm = wid >> 1, wn = wid & 1;
    int row0 = blockIdx.y * 64, col0 = blockIdx.x * 128;

    wmma::fragment<wmma::accumulator, 16, 16, 16, float> acc[2][4];
#pragma unroll
    for (int mi = 0; mi < 2; mi++)
#pragma unroll
        for (int ni = 0; ni < 4; ni++) wmma::fill_fragment(acc[mi][ni], 0.0f);

    int KT = (K + 31) >> 5;

    auto loadA = [&](int kt, int buf) {
        int k0 = kt << 5;
#pragma unroll
        for (int i = 0; i < 4; i++) {
            int v = tid + (i << 7);             // 0..511
            int r = v >> 3, c = (v & 7) << 2;
            int gr = row0 + r;
            float4 a = make_float4(0.f, 0.f, 0.f, 0.f);
            if (gr < M && k0 + c < K) a = *(const float4*)(A + (size_t)gr * lda + k0 + c);
            int idx = buf * 2560 + r * 40 + c;
            split4(a, &Ah[idx], &Am[idx]);
        }
    };
    auto loadB = [&](int kt, int buf) {
        int k0 = kt << 5;
#pragma unroll
        for (int i = 0; i < 8; i++) {
            int v = tid + (i << 7);             // 0..1023
            int r = v >> 5, c = (v & 31) << 2;
            int gc = col0 + c;
            float4 b = make_float4(0.f, 0.f, 0.f, 0.f);
            if (gc < N && k0 + r < K) b = *(const float4*)(B + (size_t)(k0 + r) * N + gc);
            int idx = buf * 4352 + r * 136 + c;
            split4(b, &Bh[idx], &Bm[idx]);
        }
    };

    loadA(0, 0); loadB(0, 0);
    __syncthreads();
    for (int kt = 0; kt < KT; kt++) {
        int buf = kt & 1;
        if (kt + 1 < KT) { loadA(kt + 1, buf ^ 1); loadB(kt + 1, buf ^ 1); }
#pragma unroll
        for (int ks = 0; ks < 2; ks++) {
            wmma::fragment<wmma::matrix_a, 16, 16, 16, __nv_bfloat16, wmma::row_major> ah[2], am[2];
            wmma::fragment<wmma::matrix_b, 16, 16, 16, __nv_bfloat16, wmma::row_major> bh[4], bm[4];
#pragma unroll
            for (int mi = 0; mi < 2; mi++) {
                int off = buf * 2560 + (wm * 32 + mi * 16) * 40 + ks * 16;
                wmma::load_matrix_sync(ah[mi], &Ah[off], 40);
                wmma::load_matrix_sync(am[mi], &Am[off], 40);
            }
#pragma unroll
            for (int ni = 0; ni < 4; ni++) {
                int off = buf * 4352 + (ks * 16) * 136 + wn * 64 + ni * 16;
                wmma::load_matrix_sync(bh[ni], &Bh[off], 136);
                wmma::load_matrix_sync(bm[ni], &Bm[off], 136);
            }
#pragma unroll
            for (int mi = 0; mi < 2; mi++)
#pragma unroll
                for (int ni = 0; ni < 4; ni++) {
                    wmma::mma_sync(acc[mi][ni], am[mi], bh[ni], acc[mi][ni]);
                    wmma::mma_sync(acc[mi][ni], ah[mi], bm[ni], acc[mi][ni]);
                    wmma::mma_sync(acc[mi][ni], ah[mi], bh[ni], acc[mi][ni]);
                }
        }
        __syncthreads();
    }

    // epilogue: reuse smem front as float staging (4 warps x 320 floats)
    float* epi = (float*)sm_raw + wid * 320;
#pragma unroll
    for (int mi = 0; mi < 2; mi++) {
#pragma unroll
        for (int ni = 0; ni < 4; ni++) {
            wmma::store_matrix_sync(epi, acc[mi][ni], 20, wmma::mem_row_major);
            __syncwarp();
            int r = lane >> 1, cb = (lane & 1) * 8;
            int m = row0 + wm * 32 + mi * 16 + r;
            int n0 = col0 + wn * 64 + ni * 16 + cb;
            if (m < M && n0 < N) {
                float rs = rowscale ? rowscale[m] : 1.0f;
                float4 v0 = *(float4*)&epi[r * 20 + cb];
                float4 v1 = *(float4*)&epi[r * 20 + cb + 4];
                if (Cin) {
                    float4 c0 = *(const float4*)(Cin + (size_t)m * ldc + n0);
                    float4 c1 = *(const float4*)(Cin + (size_t)m * ldc + n0 + 4);
                    v0.x += c0.x; v0.y += c0.y; v0.z += c0.z; v0.w += c0.w;
                    v1.x += c1.x; v1.y += c1.y; v1.z += c1.z; v1.w += c1.w;
                }
                if (bias) {
                    float4 b0 = *(const float4*)(bias + n0);
                    float4 b1 = *(const float4*)(bias + n0 + 4);
                    v0.x += rs * b0.x; v0.y += rs * b0.y; v0.z += rs * b0.z; v0.w += rs * b0.w;
                    v1.x += rs * b1.x; v1.y += rs * b1.y; v1.z += rs * b1.z; v1.w += rs * b1.w;
                }
                if (relu) {
                    v0.x = fmaxf(v0.x, 0.f); v0.y = fmaxf(v0.y, 0.f);
                    v0.z = fmaxf(v0.z, 0.f); v0.w = fmaxf(v0.w, 0.f);
                    v1.x = fmaxf(v1.x, 0.f); v1.y = fmaxf(v1.y, 0.f);
                    v1.z = fmaxf(v1.z, 0.f); v1.w = fmaxf(v1.w, 0.f);
                }
                *(float4*)(D + (size_t)m * ldd + n0)     = v0;
                *(float4*)(D + (size_t)m * ldd + n0 + 4) = v1;
            }
            __syncwarp();
        }
    }
}

// ---------------- fused EA edge pass ----------------
__global__ __launch_bounds__(256)
void k_edge_f(const float* __restrict__ P, const float* __restrict__ Q,
              const float* __restrict__ EA, const float* __restrict__ W1e,
              const float* __restrict__ b1, float* __restrict__ S) {
    __shared__ float sw[16 * 128];
    __shared__ float sb[128];
    for (int v = threadIdx.x; v < 2048; v += blockDim.x) sw[v] = W1e[v];
    for (int v = threadIdx.x; v < 128; v += blockDim.x) sb[v] = b1[v];
    __syncthreads();
    int lane = threadIdx.x & 31;
    int f = lane * 4;
    float w[16][4];
#pragma unroll
    for (int k = 0; k < 16; k++) {
        float4 t = *(const float4*)&sw[k * 128 + f];
        w[k][0] = t.x; w[k][1] = t.y; w[k][2] = t.z; w[k][3] = t.w;
    }
    float4 bb = *(const float4*)&sb[f];

    int i = (blockIdx.x * blockDim.x + threadIdx.x) >> 5;
    if (i >= NN) return;
    float4 p = *(const float4*)(P + (size_t)i * HD + f);
    float4 acc = make_float4(0.f, 0.f, 0.f, 0.f);
    int s1 = g_off[i + 1];
    for (int s = g_off[i]; s < s1; s++) {
        int src = g_csr_src[s];
        int rid = g_csr_rid[s];
        float val = (lane < 16) ? EA[(size_t)rid * 16 + lane] : 0.0f;
        float4 q = *(const float4*)(Q + (size_t)src * HD + f);
        float4 r = bb;
#pragma unroll
        for (int k = 0; k < 16; k++) {
            float a = __shfl_sync(0xffffffffu, val, k);
            r.x += a * w[k][0]; r.y += a * w[k][1];
            r.z += a * w[k][2]; r.w += a * w[k][3];
        }
        acc.x += fmaxf(p.x + q.x + r.x, 0.f);
        acc.y += fmaxf(p.y + q.y + r.y, 0.f);
        acc.z += fmaxf(p.z + q.z + r.z, 0.f);
        acc.w += fmaxf(p.w + q.w + r.w, 0.f);
    }
    *(float4*)(S + (size_t)i * HD + f) = acc;
}

// ---------------- TAG propagation (norm folded via dis), ld = 512 ----------------
__global__ __launch_bounds__(256)
void k_prop(const float* __restrict__ Xc, float* __restrict__ Xn) {
    int i = (blockIdx.x * blockDim.x + threadIdx.x) >> 5;
    if (i >= NN) return;
    int lane = threadIdx.x & 31;
    int f = lane * 4;
    float4 acc = make_float4(0.f, 0.f, 0.f, 0.f);
    int s1 = g_off[i + 1];
    for (int s = g_off[i]; s < s1; s++) {
        int src = g_csr_src[s];
        float nm = __ldg(&g_dis[src]);
        float4 h = *(const float4*)(Xc + (size_t)src * 512 + f);
        acc.x += nm * h.x; acc.y += nm * h.y;
        acc.z += nm * h.z; acc.w += nm * h.w;
    }
    float di = __ldg(&g_dis[i]);
    acc.x *= di; acc.y *= di; acc.z *= di; acc.w *= di;
    *(float4*)(Xn + (size_t)i * 512 + f) = acc;
}

// ---------------- final output: out[i] = C[i]@W2 + deg[i]*b2  (N=16) ----------------
__global__ __launch_bounds__(256)
void k_out(const float* __restrict__ C, const float* __restrict__ W2,
           const float* __restrict__ b2, float* __restrict__ out) {
    __shared__ float sw[128 * 16];
    __shared__ float sb[16];
    for (int v = threadIdx.x; v < 2048; v += blockDim.x) sw[v] = W2[v];
    if (threadIdx.x < 16) sb[threadIdx.x] = b2[threadIdx.x];
    __syncthreads();
    int gt = blockIdx.x * blockDim.x + threadIdx.x;
    int i = gt >> 5;
    if (i >= NN) return;
    int lane = threadIdx.x & 31, f = lane * 4;
    float4 c = *(const float4*)(C + (size_t)i * HD + f);
    float o[16];
#pragma unroll
    for (int t = 0; t < 16; t++) o[t] = 0.0f;
    float cv[4] = {c.x, c.y, c.z, c.w};
#pragma unroll
    for (int j = 0; j < 4; j++) {
        const float* wr = &sw[(f + j) * 16];
        float cj = cv[j];
#pragma unroll
        for (int t = 0; t < 16; t++) o[t] += cj * wr[t];
    }
#pragma unroll
    for (int off = 16; off > 0; off >>= 1)
#pragma unroll
        for (int t = 0; t < 16; t++) o[t] += __shfl_xor_sync(0xffffffffu, o[t], off);
    if (lane < 16)
        out[(size_t)i * 16 + lane] = o[lane] + g_degf[i] * sb[lane];
}

// ---------------- host ----------------
static void gemm(const float* A, int lda, const float* B, long bStride,
                 float* D, int ldd, long dStride,
                 const float* Cin, int ldc, const float* bias, const float* rowscale,
                 int M, int K, int N, int relu, int batch) {
    dim3 grid((N + 127) / 128, (M + 63) / 64, batch);
    k_gemm_tc<<<grid, 128, GEMM_SMEM>>>(A, lda, B, bStride, D, ldd, dStride,
                                        Cin, ldc, bias, rowscale, M, K, N, relu);
}

extern "C" void kernel_launch(void* const* d_in, const int* in_sizes, int n_in,
                              void* d_out, int out_size) {
    const float* x         = (const float*)d_in[0];
    const float* mask      = (const float*)d_in[1];
    const float* edge_attr = (const float*)d_in[2];
    const int* edge_index;
    int base;
    if (in_sizes[3] == 2 * EE) {
        edge_index = (const int*)d_in[3];
        base = 4;
    } else {
        edge_index = (const int*)d_in[n_in - 1];
        base = 3;
    }
    const float* m_w1   = (const float*)d_in[base + 0];
    const float* m_b1   = (const float*)d_in[base + 1];
    const float* m_w2   = (const float*)d_in[base + 2];
    const float* m_b2   = (const float*)d_in[base + 3];
    const float* ea0_w1 = (const float*)d_in[base + 4];
    const float* ea0_b1 = (const float*)d_in[base + 5];
    const float* ea0_w2 = (const float*)d_in[base + 6];
    const float* ea0_b2 = (const float*)d_in[base + 7];
    const float* tag0_w = (const float*)d_in[base + 8];
    const float* tag0_b = (const float*)d_in[base + 9];
    const float* ea1_w1 = (const float*)d_in[base + 10];
    const float* ea1_b1 = (const float*)d_in[base + 11];
    const float* ea1_w2 = (const float*)d_in[base + 12];
    const float* ea1_b2 = (const float*)d_in[base + 13];
    const float* tag1_w = (const float*)d_in[base + 14];
    const float* tag1_b = (const float*)d_in[base + 15];
    const float* ea2_w1 = (const float*)d_in[base + 16];
    const float* ea2_b1 = (const float*)d_in[base + 17];
    const float* ea2_w2 = (const float*)d_in[base + 18];
    const float* ea2_b2 = (const float*)d_in[base + 19];

    float *pAB, *pC, *pH, *pX, *ph16, *pdegf;
    cudaGetSymbolAddress((void**)&pAB, g_AB);
    cudaGetSymbolAddress((void**)&pC, g_C);
    cudaGetSymbolAddress((void**)&pH, g_H);
    cudaGetSymbolAddress((void**)&pX, g_X);
    cudaGetSymbolAddress((void**)&ph16, g_h16);
    cudaGetSymbolAddress((void**)&pdegf, g_degf);
    float* pA = pAB;
    float* pB = pAB + (size_t)NN * HD;

    static int smem_set = 0;
    if (!smem_set) {
        cudaFuncSetAttribute(k_gemm_tc, cudaFuncAttributeMaxDynamicSharedMemorySize, GEMM_SMEM);
        smem_set = 1;
    }

    const int EB = 2500;              // 20000 node-warps / 8 warps per block
    const long NSTR = (long)NN * HD;

    k_mask<<<EB, 256>>>(mask, x, m_w1, m_b1, m_w2, m_b2, ph16);
    k_hist<<<(EE + 255) / 256, 256>>>(edge_index);
    k_scan<<<1, 1024>>>();
    k_fill<<<(EE + 255) / 256, 256>>>(edge_index);

    // ---- EA0 (in=16) ----
    gemm(ph16, 16, ea0_w1, 16 * 128, pAB, 128, NSTR, nullptr, 0, nullptr, nullptr,
         NN, 16, 128, 0, 2);
    k_edge_f<<<EB, 256>>>(pA, pB, edge_attr, ea0_w1 + 32 * 128, ea0_b1, pC);
    gemm(pC, 128, ea0_w2, 0, pX, 512, 0, nullptr, 0, ea0_b2, pdegf, NN, 128, 128, 1, 1);

    // ---- TAG0 ----
    k_prop<<<EB, 256>>>(pX,       pX + 128);
    k_prop<<<EB, 256>>>(pX + 128, pX + 256);
    k_prop<<<EB, 256>>>(pX + 256, pX + 384);
    gemm(pX, 512, tag0_w, 0, pH, 128, 0, nullptr, 0, tag0_b, nullptr, NN, 512, 128, 1, 1);

    // ---- EA1 (in=128) ----
    gemm(pH, 128, ea1_w1, 128 * 128, pAB, 128, NSTR, nullptr, 0, nullptr, nullptr,
         NN, 128, 128, 0, 2);
    k_edge_f<<<EB, 256>>>(pA, pB, edge_attr, ea1_w1 + 256 * 128, ea1_b1, pC);
    gemm(pC, 128, ea1_w2, 0, pX, 512, 0, nullptr, 0, ea1_b2, pdegf, NN, 128, 128, 1, 1);

    // ---- TAG1 ----
    k_prop<<<EB, 256>>>(pX,       pX + 128);
    k_prop<<<EB, 256>>>(pX + 128, pX + 256);
    k_prop<<<EB, 256>>>(pX + 256, pX + 384);
    gemm(pX, 512, tag1_w, 0, pH, 128, 0, nullptr, 0, tag1_b, nullptr, NN, 512, 128, 1, 1);

    // ---- EA2 (final) ----
    gemm(pH, 128, ea2_w1, 128 * 128, pAB, 128, NSTR, nullptr, 0, nullptr, nullptr,
         NN, 128, 128, 0, 2);
    k_edge_f<<<EB, 256>>>(pA, pB, edge_attr, ea2_w1 + 256 * 128, ea2_b1, pC);
    k_out<<<EB, 256>>>(pC, ea2_w2, ea2_b2, (float*)d_out);
}

// round 10
// speedup vs baseline: 1.3132x; 1.0006x over previous
#include <cuda_runtime.h>
#include <cuda_bf16.h>
#include <mma.h>
#include <cstdint>

#define NN 20000
#define EE 160000
#define E2 320000
#define HD 128

// ---------------- static scratch (no allocations allowed) ----------------
static __device__ float g_AB[2 * NN * HD];       // P | Q projections (contiguous for grid.z)
static __device__ float g_C[NN * HD];
static __device__ float g_H[NN * HD];
static __device__ float g_X[(size_t)NN * 512];   // [h | Lh | L^2h | L^3h]
static __device__ float g_h16[NN * 16];
static __device__ float g_degf[NN];
static __device__ float g_dis[NN];
static __device__ int   g_deg[NN];
static __device__ int   g_cnt[NN];
static __device__ int   g_off[NN + 1];
static __device__ int   g_csr_src[E2];
static __device__ int   g_csr_rid[E2];

// ---------------- fused mask MLP (+ zero g_deg) ----------------
__global__ __launch_bounds__(256)
void k_mask(const float* __restrict__ mask, const float* __restrict__ x,
            const float* __restrict__ w1, const float* __restrict__ b1,
            const float* __restrict__ w2, const float* __restrict__ b2,
            float* __restrict__ out) {
    __shared__ float sw1[16 * 128];
    __shared__ float sb1[128];
    __shared__ float sw2[128 * 16];
    __shared__ float sb2[16];
    for (int v = threadIdx.x; v < 2048; v += blockDim.x) { sw1[v] = w1[v]; sw2[v] = w2[v]; }
    for (int v = threadIdx.x; v < 128; v += blockDim.x) sb1[v] = b1[v];
    if (threadIdx.x < 16) sb2[threadIdx.x] = b2[threadIdx.x];

    int gt = blockIdx.x * blockDim.x + threadIdx.x;
    if (gt < NN) g_deg[gt] = 0;
    __syncthreads();

    int i = gt >> 5;
    if (i >= NN) return;
    int lane = threadIdx.x & 31;
    int f = lane * 4;
    float m = (lane < 16) ? mask[(size_t)i * 16 + lane] : 0.0f;
    float4 h = *(const float4*)&sb1[f];
#pragma unroll
    for (int k = 0; k < 16; k++) {
        float a = __shfl_sync(0xffffffffu, m, k);
        const float4 w = *(const float4*)&sw1[k * 128 + f];
        h.x += a * w.x; h.y += a * w.y; h.z += a * w.z; h.w += a * w.w;
    }
    h.x = fmaxf(h.x, 0.f); h.y = fmaxf(h.y, 0.f);
    h.z = fmaxf(h.z, 0.f); h.w = fmaxf(h.w, 0.f);

    float o[16];
#pragma unroll
    for (int t = 0; t < 16; t++) o[t] = 0.0f;
    float hv[4] = {h.x, h.y, h.z, h.w};
#pragma unroll
    for (int j = 0; j < 4; j++) {
        const float* wrow = &sw2[(f + j) * 16];
        float hj = hv[j];
#pragma unroll
        for (int t = 0; t < 16; t++) o[t] += hj * wrow[t];
    }
#pragma unroll
    for (int off = 16; off > 0; off >>= 1)
#pragma unroll
        for (int t = 0; t < 16; t++) o[t] += __shfl_xor_sync(0xffffffffu, o[t], off);
    if (lane < 16)
        out[(size_t)i * 16 + lane] = o[lane] + sb2[lane] + x[(size_t)i * 16 + lane];
}

// ---------------- CSR build ----------------
__global__ void k_hist(const int* __restrict__ ei) {
    int e = blockIdx.x * blockDim.x + threadIdx.x;
    if (e >= EE) return;
    int s = ei[e], d = ei[EE + e];
    atomicAdd(&g_deg[d], 1);
    atomicAdd(&g_deg[s], 1);
}

__global__ void k_scan() {
    __shared__ int part[1024];
    const int CH = (NN + 1023) / 1024;
    int t = threadIdx.x;
    int base = t * CH;
    int s = 0;
    for (int j = 0; j < CH; j++) {
        int idx = base + j;
        if (idx < NN) s += g_deg[idx];
    }
    part[t] = s;
    __syncthreads();
    for (int off = 1; off < 1024; off <<= 1) {
        int v = (t >= off) ? part[t - off] : 0;
        __syncthreads();
        part[t] += v;
        __syncthreads();
    }
    int run = (t > 0) ? part[t - 1] : 0;
    for (int j = 0; j < CH; j++) {
        int idx = base + j;
        if (idx < NN) {
            g_off[idx] = run;
            int d = g_deg[idx];
            run += d;
            g_cnt[idx] = 0;
            g_degf[idx] = (float)d;
            g_dis[idx]  = (d > 0) ? rsqrtf((float)d) : 0.0f;
        }
    }
    if (t == 1023) g_off[NN] = run;
}

__global__ void k_fill(const int* __restrict__ ei) {
    int e = blockIdx.x * blockDim.x + threadIdx.x;
    if (e >= EE) return;
    int s0 = ei[e], d0 = ei[EE + e];
    int p = atomicAdd(&g_cnt[d0], 1);
    int slot = g_off[d0] + p;
    g_csr_src[slot] = s0;
    g_csr_rid[slot] = e;
    p = atomicAdd(&g_cnt[s0], 1);
    slot = g_off[s0] + p;
    g_csr_src[slot] = d0;
    g_csr_rid[slot] = e;
}

// ---------------- bf16x3 tensor-core GEMM ----------------
// D[M,N] = A[M,K]@B[K,N] (+Cin)(+rowscale*bias)(relu), emulated fp32 via
// bf16 hi/mid split: acc += am*bh + ah*bm + ah*bh (am*bm ~2^-16 dropped).
// CTA tile 64x128, 4 warps (2m x 2n), warp tile 32x64, BK=32 double-buffered.
__device__ __forceinline__ void split4(float4 a, __nv_bfloat16* ph, __nv_bfloat16* pm) {
    __nv_bfloat162 h0 = __floats2bfloat162_rn(a.x, a.y);
    __nv_bfloat162 h1 = __floats2bfloat162_rn(a.z, a.w);
    __nv_bfloat162 m0 = __floats2bfloat162_rn(a.x - __bfloat162float(h0.x),
                                              a.y - __bfloat162float(h0.y));
    __nv_bfloat162 m1 = __floats2bfloat162_rn(a.z - __bfloat162float(h1.x),
                                              a.w - __bfloat162float(h1.y));
    *(__nv_bfloat162*)ph = h0; *(__nv_bfloat162*)(ph + 2) = h1;
    *(__nv_bfloat162*)pm = m0; *(__nv_bfloat162*)(pm + 2) = m1;
}

#define GEMM_SMEM 55296
// layout in halves: Ah[2][2560] (ld 40), Am[2][2560], Bh[2][4352] (ld 136), Bm[2][4352]

__global__ __launch_bounds__(128)
void k_gemm_tc(const float* __restrict__ A, int lda,
               const float* __restrict__ B, long bStride,
               float* __restrict__ D, int ldd, long dStride,
               const float* __restrict__ Cin, int ldc,
               const float* __restrict__ bias, const float* __restrict__ rowscale,
               int M, int K, int N, int relu) {
    using namespace nvcuda;
    extern __shared__ char sm_raw[];
    __nv_bfloat16* Ah = (__nv_bfloat16*)sm_raw;
    __nv_bfloat16* Am = Ah + 2 * 2560;
    __nv_bfloat16* Bh = Am + 2 * 2560;
    __nv_bfloat16* Bm = Bh + 2 * 4352;

    B += (size_t)blockIdx.z * bStride;
    D += (size_t)blockIdx.z * dStride;

    int tid = threadIdx.x;
    int wid = tid >> 5, lane = tid & 31;
    int wm = wid >> 1, wn = wid & 1;
    int row0 = blockIdx.y * 64, col0 = blockIdx.x * 128;

    wmma::fragment<wmma::accumulator, 16, 16, 16, float> acc[2][4];
#pragma unroll
    for (int mi = 0; mi < 2; mi++)
#pragma unroll
        for (int ni = 0; ni < 4; ni++) wmma::fill_fragment(acc[mi][ni], 0.0f);

    int KT = (K + 31) >> 5;

    auto loadA = [&](int kt, int buf) {
        int k0 = kt << 5;
#pragma unroll
        for (int i = 0; i < 4; i++) {
            int v = tid + (i << 7);             // 0..511
            int r = v >> 3, c = (v & 7) << 2;
            int gr = row0 + r;
            float4 a = make_float4(0.f, 0.f, 0.f, 0.f);
            if (gr < M && k0 + c < K) a = *(const float4*)(A + (size_t)gr * lda + k0 + c);
            int idx = buf * 2560 + r * 40 + c;
            split4(a, &Ah[idx], &Am[idx]);
        }
    };
    auto loadB = [&](int kt, int buf) {
        int k0 = kt << 5;
#pragma unroll
        for (int i = 0; i < 8; i++) {
            int v = tid + (i << 7);             // 0..1023
            int r = v >> 5, c = (v & 31) << 2;
            int gc = col0 + c;
            float4 b = make_float4(0.f, 0.f, 0.f, 0.f);
            if (gc < N && k0 + r < K) b = *(const float4*)(B + (size_t)(k0 + r) * N + gc);
            int idx = buf * 4352 + r * 136 + c;
            split4(b, &Bh[idx], &Bm[idx]);
        }
    };

    loadA(0, 0); loadB(0, 0);
    __syncthreads();
    for (int kt = 0; kt < KT; kt++) {
        int buf = kt & 1;
        if (kt + 1 < KT) { loadA(kt + 1, buf ^ 1); loadB(kt + 1, buf ^ 1); }
#pragma unroll
        for (int ks = 0; ks < 2; ks++) {
            wmma::fragment<wmma::matrix_a, 16, 16, 16, __nv_bfloat16, wmma::row_major> ah[2], am[2];
            wmma::fragment<wmma::matrix_b, 16, 16, 16, __nv_bfloat16, wmma::row_major> bh[4], bm[4];
#pragma unroll
            for (int mi = 0; mi < 2; mi++) {
                int off = buf * 2560 + (wm * 32 + mi * 16) * 40 + ks * 16;
                wmma::load_matrix_sync(ah[mi], &Ah[off], 40);
                wmma::load_matrix_sync(am[mi], &Am[off], 40);
            }
#pragma unroll
            for (int ni = 0; ni < 4; ni++) {
                int off = buf * 4352 + (ks * 16) * 136 + wn * 64 + ni * 16;
                wmma::load_matrix_sync(bh[ni], &Bh[off], 136);
                wmma::load_matrix_sync(bm[ni], &Bm[off], 136);
            }
#pragma unroll
            for (int mi = 0; mi < 2; mi++)
#pragma unroll
                for (int ni = 0; ni < 4; ni++) {
                    wmma::mma_sync(acc[mi][ni], am[mi], bh[ni], acc[mi][ni]);
                    wmma::mma_sync(acc[mi][ni], ah[mi], bm[ni], acc[mi][ni]);
                    wmma::mma_sync(acc[mi][ni], ah[mi], bh[ni], acc[mi][ni]);
                }
        }
        __syncthreads();
    }

    // epilogue: reuse smem front as float staging (4 warps x 320 floats)
    float* epi = (float*)sm_raw + wid * 320;
#pragma unroll
    for (int mi = 0; mi < 2; mi++) {
#pragma unroll
        for (int ni = 0; ni < 4; ni++) {
            wmma::store_matrix_sync(epi, acc[mi][ni], 20, wmma::mem_row_major);
            __syncwarp();
            int r = lane >> 1, cb = (lane & 1) * 8;
            int m = row0 + wm * 32 + mi * 16 + r;
            int n0 = col0 + wn * 64 + ni * 16 + cb;
            if (m < M && n0 < N) {
                float rs = rowscale ? rowscale[m] : 1.0f;
                float4 v0 = *(float4*)&epi[r * 20 + cb];
                float4 v1 = *(float4*)&epi[r * 20 + cb + 4];
                if (Cin) {
                    float4 c0 = *(const float4*)(Cin + (size_t)m * ldc + n0);
                    float4 c1 = *(const float4*)(Cin + (size_t)m * ldc + n0 + 4);
                    v0.x += c0.x; v0.y += c0.y; v0.z += c0.z; v0.w += c0.w;
                    v1.x += c1.x; v1.y += c1.y; v1.z += c1.z; v1.w += c1.w;
                }
                if (bias) {
                    float4 b0 = *(const float4*)(bias + n0);
                    float4 b1 = *(const float4*)(bias + n0 + 4);
                    v0.x += rs * b0.x; v0.y += rs * b0.y; v0.z += rs * b0.z; v0.w += rs * b0.w;
                    v1.x += rs * b1.x; v1.y += rs * b1.y; v1.z += rs * b1.z; v1.w += rs * b1.w;
                }
                if (relu) {
                    v0.x = fmaxf(v0.x, 0.f); v0.y = fmaxf(v0.y, 0.f);
                    v0.z = fmaxf(v0.z, 0.f); v0.w = fmaxf(v0.w, 0.f);
                    v1.x = fmaxf(v1.x, 0.f); v1.y = fmaxf(v1.y, 0.f);
                    v1.z = fmaxf(v1.z, 0.f); v1.w = fmaxf(v1.w, 0.f);
                }
                *(float4*)(D + (size_t)m * ldd + n0)     = v0;
                *(float4*)(D + (size_t)m * ldd + n0 + 4) = v1;
            }
            __syncwarp();
        }
    }
}

// ---------------- fused EA edge pass ----------------
__global__ __launch_bounds__(256)
void k_edge_f(const float* __restrict__ P, const float* __restrict__ Q,
              const float* __restrict__ EA, const float* __restrict__ W1e,
              const float* __restrict__ b1, float* __restrict__ S) {
    __shared__ float sw[16 * 128];
    __shared__ float sb[128];
    for (int v = threadIdx.x; v < 2048; v += blockDim.x) sw[v] = W1e[v];
    for (int v = threadIdx.x; v < 128; v += blockDim.x) sb[v] = b1[v];
    __syncthreads();
    int lane = threadIdx.x & 31;
    int f = lane * 4;
    float w[16][4];
#pragma unroll
    for (int k = 0; k < 16; k++) {
        float4 t = *(const float4*)&sw[k * 128 + f];
        w[k][0] = t.x; w[k][1] = t.y; w[k][2] = t.z; w[k][3] = t.w;
    }
    float4 bb = *(const float4*)&sb[f];

    int i = (blockIdx.x * blockDim.x + threadIdx.x) >> 5;
    if (i >= NN) return;
    float4 p = *(const float4*)(P + (size_t)i * HD + f);
    float4 acc = make_float4(0.f, 0.f, 0.f, 0.f);
    int s1 = g_off[i + 1];
    for (int s = g_off[i]; s < s1; s++) {
        int src = g_csr_src[s];
        int rid = g_csr_rid[s];
        float val = (lane < 16) ? EA[(size_t)rid * 16 + lane] : 0.0f;
        float4 q = *(const float4*)(Q + (size_t)src * HD + f);
        float4 r = bb;
#pragma unroll
        for (int k = 0; k < 16; k++) {
            float a = __shfl_sync(0xffffffffu, val, k);
            r.x += a * w[k][0]; r.y += a * w[k][1];
            r.z += a * w[k][2]; r.w += a * w[k][3];
        }
        acc.x += fmaxf(p.x + q.x + r.x, 0.f);
        acc.y += fmaxf(p.y + q.y + r.y, 0.f);
        acc.z += fmaxf(p.z + q.z + r.z, 0.f);
        acc.w += fmaxf(p.w + q.w + r.w, 0.f);
    }
    *(float4*)(S + (size_t)i * HD + f) = acc;
}

// ---------------- TAG propagation (norm folded via dis), ld = 512 ----------------
__global__ __launch_bounds__(256)
void k_prop(const float* __restrict__ Xc, float* __restrict__ Xn) {
    int i = (blockIdx.x * blockDim.x + threadIdx.x) >> 5;
    if (i >= NN) return;
    int lane = threadIdx.x & 31;
    int f = lane * 4;
    float4 acc = make_float4(0.f, 0.f, 0.f, 0.f);
    int s1 = g_off[i + 1];
    for (int s = g_off[i]; s < s1; s++) {
        int src = g_csr_src[s];
        float nm = __ldg(&g_dis[src]);
        float4 h = *(const float4*)(Xc + (size_t)src * 512 + f);
        acc.x += nm * h.x; acc.y += nm * h.y;
        acc.z += nm * h.z; acc.w += nm * h.w;
    }
    float di = __ldg(&g_dis[i]);
    acc.x *= di; acc.y *= di; acc.z *= di; acc.w *= di;
    *(float4*)(Xn + (size_t)i * 512 + f) = acc;
}

// ---------------- final output: out[i] = C[i]@W2 + deg[i]*b2  (N=16) ----------------
__global__ __launch_bounds__(256)
void k_out(const float* __restrict__ C, const float* __restrict__ W2,
           const float* __restrict__ b2, float* __restrict__ out) {
    __shared__ float sw[128 * 16];
    __shared__ float sb[16];
    for (int v = threadIdx.x; v < 2048; v += blockDim.x) sw[v] = W2[v];
    if (threadIdx.x < 16) sb[threadIdx.x] = b2[threadIdx.x];
    __syncthreads();
    int gt = blockIdx.x * blockDim.x + threadIdx.x;
    int i = gt >> 5;
    if (i >= NN) return;
    int lane = threadIdx.x & 31, f = lane * 4;
    float4 c = *(const float4*)(C + (size_t)i * HD + f);
    float o[16];
#pragma unroll
    for (int t = 0; t < 16; t++) o[t] = 0.0f;
    float cv[4] = {c.x, c.y, c.z, c.w};
#pragma unroll
    for (int j = 0; j < 4; j++) {
        const float* wr = &sw[(f + j) * 16];
        float cj = cv[j];
#pragma unroll
        for (int t = 0; t < 16; t++) o[t] += cj * wr[t];
    }
#pragma unroll
    for (int off = 16; off > 0; off >>= 1)
#pragma unroll
        for (int t = 0; t < 16; t++) o[t] += __shfl_xor_sync(0xffffffffu, o[t], off);
    if (lane < 16)
        out[(size_t)i * 16 + lane] = o[lane] + g_degf[i] * sb[lane];
}

// ---------------- host ----------------
static void gemm(const float* A, int lda, const float* B, long bStride,
                 float* D, int ldd, long dStride,
                 const float* Cin, int ldc, const float* bias, const float* rowscale,
                 int M, int K, int N, int relu, int batch) {
    dim3 grid((N + 127) / 128, (M + 63) / 64, batch);
    k_gemm_tc<<<grid, 128, GEMM_SMEM>>>(A, lda, B, bStride, D, ldd, dStride,
                                        Cin, ldc, bias, rowscale, M, K, N, relu);
}

extern "C" void kernel_launch(void* const* d_in, const int* in_sizes, int n_in,
                              void* d_out, int out_size) {
    const float* x         = (const float*)d_in[0];
    const float* mask      = (const float*)d_in[1];
    const float* edge_attr = (const float*)d_in[2];
    const int* edge_index;
    int base;
    if (in_sizes[3] == 2 * EE) {
        edge_index = (const int*)d_in[3];
        base = 4;
    } else {
        edge_index = (const int*)d_in[n_in - 1];
        base = 3;
    }
    const float* m_w1   = (const float*)d_in[base + 0];
    const float* m_b1   = (const float*)d_in[base + 1];
    const float* m_w2   = (const float*)d_in[base + 2];
    const float* m_b2   = (const float*)d_in[base + 3];
    const float* ea0_w1 = (const float*)d_in[base + 4];
    const float* ea0_b1 = (const float*)d_in[base + 5];
    const float* ea0_w2 = (const float*)d_in[base + 6];
    const float* ea0_b2 = (const float*)d_in[base + 7];
    const float* tag0_w = (const float*)d_in[base + 8];
    const float* tag0_b = (const float*)d_in[base + 9];
    const float* ea1_w1 = (const float*)d_in[base + 10];
    const float* ea1_b1 = (const float*)d_in[base + 11];
    const float* ea1_w2 = (const float*)d_in[base + 12];
    const float* ea1_b2 = (const float*)d_in[base + 13];
    const float* tag1_w = (const float*)d_in[base + 14];
    const float* tag1_b = (const float*)d_in[base + 15];
    const float* ea2_w1 = (const float*)d_in[base + 16];
    const float* ea2_b1 = (const float*)d_in[base + 17];
    const float* ea2_w2 = (const float*)d_in[base + 18];
    const float* ea2_b2 = (const float*)d_in[base + 19];

    float *pAB, *pC, *pH, *pX, *ph16, *pdegf;
    cudaGetSymbolAddress((void**)&pAB, g_AB);
    cudaGetSymbolAddress((void**)&pC, g_C);
    cudaGetSymbolAddress((void**)&pH, g_H);
    cudaGetSymbolAddress((void**)&pX, g_X);
    cudaGetSymbolAddress((void**)&ph16, g_h16);
    cudaGetSymbolAddress((void**)&pdegf, g_degf);
    float* pA = pAB;
    float* pB = pAB + (size_t)NN * HD;

    static int smem_set = 0;
    if (!smem_set) {
        cudaFuncSetAttribute(k_gemm_tc, cudaFuncAttributeMaxDynamicSharedMemorySize, GEMM_SMEM);
        smem_set = 1;
    }

    const int EB = 2500;              // 20000 node-warps / 8 warps per block
    const long NSTR = (long)NN * HD;

    k_mask<<<EB, 256>>>(mask, x, m_w1, m_b1, m_w2, m_b2, ph16);
    k_hist<<<(EE + 255) / 256, 256>>>(edge_index);
    k_scan<<<1, 1024>>>();
    k_fill<<<(EE + 255) / 256, 256>>>(edge_index);

    // ---- EA0 (in=16) ----
    gemm(ph16, 16, ea0_w1, 16 * 128, pAB, 128, NSTR, nullptr, 0, nullptr, nullptr,
         NN, 16, 128, 0, 2);
    k_edge_f<<<EB, 256>>>(pA, pB, edge_attr, ea0_w1 + 32 * 128, ea0_b1, pC);
    gemm(pC, 128, ea0_w2, 0, pX, 512, 0, nullptr, 0, ea0_b2, pdegf, NN, 128, 128, 1, 1);

    // ---- TAG0 ----
    k_prop<<<EB, 256>>>(pX,       pX + 128);
    k_prop<<<EB, 256>>>(pX + 128, pX + 256);
    k_prop<<<EB, 256>>>(pX + 256, pX + 384);
    gemm(pX, 512, tag0_w, 0, pH, 128, 0, nullptr, 0, tag0_b, nullptr, NN, 512, 128, 1, 1);

    // ---- EA1 (in=128) ----
    gemm(pH, 128, ea1_w1, 128 * 128, pAB, 128, NSTR, nullptr, 0, nullptr, nullptr,
         NN, 128, 128, 0, 2);
    k_edge_f<<<EB, 256>>>(pA, pB, edge_attr, ea1_w1 + 256 * 128, ea1_b1, pC);
    gemm(pC, 128, ea1_w2, 0, pX, 512, 0, nullptr, 0, ea1_b2, pdegf, NN, 128, 128, 1, 1);

    // ---- TAG1 ----
    k_prop<<<EB, 256>>>(pX,       pX + 128);
    k_prop<<<EB, 256>>>(pX + 128, pX + 256);
    k_prop<<<EB, 256>>>(pX + 256, pX + 384);
    gemm(pX, 512, tag1_w, 0, pH, 128, 0, nullptr, 0, tag1_b, nullptr, NN, 512, 128, 1, 1);

    // ---- EA2 (final) ----
    gemm(pH, 128, ea2_w1, 128 * 128, pAB, 128, NSTR, nullptr, 0, nullptr, nullptr,
         NN, 128, 128, 0, 2);
    k_edge_f<<<EB, 256>>>(pA, pB, edge_attr, ea2_w1 + 256 * 128, ea2_b1, pC);
    k_out<<<EB, 256>>>(pC, ea2_w2, ea2_b2, (float*)d_out);
}

// round 11
// speedup vs baseline: 1.3197x; 1.0050x over previous
#include <cuda_runtime.h>
#include <cuda_bf16.h>
#include <mma.h>
#include <cstdint>

#define NN 20000
#define EE 160000
#define E2 320000
#define HD 128

// ---------------- static scratch (no allocations allowed) ----------------
static __device__ float g_PQ[(size_t)NN * 256];  // interleaved: cols 0-127 = P(dst), 128-255 = Q(src)
static __device__ float g_C[NN * HD];
static __device__ float g_H[NN * HD];
static __device__ float g_X[(size_t)NN * 512];   // [h | Lh | L^2h | L^3h]
static __device__ float g_h16[NN * 16];
static __device__ float g_degf[NN];
static __device__ float g_dis[NN];
static __device__ int   g_deg[NN];
static __device__ int   g_cnt[NN];
static __device__ int   g_off[NN + 1];
static __device__ int   g_csr_src[E2];
static __device__ int   g_csr_rid[E2];

// ---------------- fused mask MLP (+ zero g_deg) ----------------
__global__ __launch_bounds__(256)
void k_mask(const float* __restrict__ mask, const float* __restrict__ x,
            const float* __restrict__ w1, const float* __restrict__ b1,
            const float* __restrict__ w2, const float* __restrict__ b2,
            float* __restrict__ out) {
    __shared__ float sw1[16 * 128];
    __shared__ float sb1[128];
    __shared__ float sw2[128 * 16];
    __shared__ float sb2[16];
    for (int v = threadIdx.x; v < 2048; v += blockDim.x) { sw1[v] = w1[v]; sw2[v] = w2[v]; }
    for (int v = threadIdx.x; v < 128; v += blockDim.x) sb1[v] = b1[v];
    if (threadIdx.x < 16) sb2[threadIdx.x] = b2[threadIdx.x];

    int gt = blockIdx.x * blockDim.x + threadIdx.x;
    if (gt < NN) g_deg[gt] = 0;
    __syncthreads();

    int i = gt >> 5;
    if (i >= NN) return;
    int lane = threadIdx.x & 31;
    int f = lane * 4;
    float m = (lane < 16) ? mask[(size_t)i * 16 + lane] : 0.0f;
    float4 h = *(const float4*)&sb1[f];
#pragma unroll
    for (int k = 0; k < 16; k++) {
        float a = __shfl_sync(0xffffffffu, m, k);
        const float4 w = *(const float4*)&sw1[k * 128 + f];
        h.x += a * w.x; h.y += a * w.y; h.z += a * w.z; h.w += a * w.w;
    }
    h.x = fmaxf(h.x, 0.f); h.y = fmaxf(h.y, 0.f);
    h.z = fmaxf(h.z, 0.f); h.w = fmaxf(h.w, 0.f);

    float o[16];
#pragma unroll
    for (int t = 0; t < 16; t++) o[t] = 0.0f;
    float hv[4] = {h.x, h.y, h.z, h.w};
#pragma unroll
    for (int j = 0; j < 4; j++) {
        const float* wrow = &sw2[(f + j) * 16];
        float hj = hv[j];
#pragma unroll
        for (int t = 0; t < 16; t++) o[t] += hj * wrow[t];
    }
#pragma unroll
    for (int off = 16; off > 0; off >>= 1)
#pragma unroll
        for (int t = 0; t < 16; t++) o[t] += __shfl_xor_sync(0xffffffffu, o[t], off);
    if (lane < 16)
        out[(size_t)i * 16 + lane] = o[lane] + sb2[lane] + x[(size_t)i * 16 + lane];
}

// ---------------- CSR build ----------------
__global__ void k_hist(const int* __restrict__ ei) {
    int e = blockIdx.x * blockDim.x + threadIdx.x;
    if (e >= EE) return;
    int s = ei[e], d = ei[EE + e];
    atomicAdd(&g_deg[d], 1);
    atomicAdd(&g_deg[s], 1);
}

__global__ void k_scan() {
    __shared__ int part[1024];
    const int CH = (NN + 1023) / 1024;
    int t = threadIdx.x;
    int base = t * CH;
    int s = 0;
    for (int j = 0; j < CH; j++) {
        int idx = base + j;
        if (idx < NN) s += g_deg[idx];
    }
    part[t] = s;
    __syncthreads();
    for (int off = 1; off < 1024; off <<= 1) {
        int v = (t >= off) ? part[t - off] : 0;
        __syncthreads();
        part[t] += v;
        __syncthreads();
    }
    int run = (t > 0) ? part[t - 1] : 0;
    for (int j = 0; j < CH; j++) {
        int idx = base + j;
        if (idx < NN) {
            g_off[idx] = run;
            int d = g_deg[idx];
            run += d;
            g_cnt[idx] = 0;
            g_degf[idx] = (float)d;
            g_dis[idx]  = (d > 0) ? rsqrtf((float)d) : 0.0f;
        }
    }
    if (t == 1023) g_off[NN] = run;
}

__global__ void k_fill(const int* __restrict__ ei) {
    int e = blockIdx.x * blockDim.x + threadIdx.x;
    if (e >= EE) return;
    int s0 = ei[e], d0 = ei[EE + e];
    int p = atomicAdd(&g_cnt[d0], 1);
    int slot = g_off[d0] + p;
    g_csr_src[slot] = s0;
    g_csr_rid[slot] = e;
    p = atomicAdd(&g_cnt[s0], 1);
    slot = g_off[s0] + p;
    g_csr_src[slot] = d0;
    g_csr_rid[slot] = e;
}

// ---------------- bf16x3 tensor-core GEMM, 8 warps ----------------
// D[M,N] = A[M,K]@B[K,N] (+Cin)(+rowscale*bias)(relu), fp32 emulated via
// bf16 hi/mid split: acc += am*bh + ah*bm + ah*bh.
// CTA tile 64x128, 8 warps (4m x 2n), warp tile 16x64, BK=32 double-buffered.
__device__ __forceinline__ void split4(float4 a, __nv_bfloat16* ph, __nv_bfloat16* pm) {
    __nv_bfloat162 h0 = __floats2bfloat162_rn(a.x, a.y);
    __nv_bfloat162 h1 = __floats2bfloat162_rn(a.z, a.w);
    __nv_bfloat162 m0 = __floats2bfloat162_rn(a.x - __bfloat162float(h0.x),
                                              a.y - __bfloat162float(h0.y));
    __nv_bfloat162 m1 = __floats2bfloat162_rn(a.z - __bfloat162float(h1.x),
                                              a.w - __bfloat162float(h1.y));
    *(__nv_bfloat162*)ph = h0; *(__nv_bfloat162*)(ph + 2) = h1;
    *(__nv_bfloat162*)pm = m0; *(__nv_bfloat162*)(pm + 2) = m1;
}

#define GEMM_SMEM 55296
// halves layout: Ah[2][2560] (ld 40), Am[2][2560], Bh[2][4352] (ld 136), Bm[2][4352]

__global__ __launch_bounds__(256)
void k_gemm_tc(const float* __restrict__ A, int lda,
               const float* __restrict__ B, long bStride,
               float* __restrict__ D, int ldd, long dStride,
               const float* __restrict__ Cin, int ldc,
               const float* __restrict__ bias, const float* __restrict__ rowscale,
               int M, int K, int N, int relu) {
    using namespace nvcuda;
    extern __shared__ char sm_raw[];
    __nv_bfloat16* Ah = (__nv_bfloat16*)sm_raw;
    __nv_bfloat16* Am = Ah + 2 * 2560;
    __nv_bfloat16* Bh = Am + 2 * 2560;
    __nv_bfloat16* Bm = Bh + 2 * 4352;

    B += (size_t)blockIdx.z * bStride;
    D += (size_t)blockIdx.z * dStride;

    int tid = threadIdx.x;
    int wid = tid >> 5, lane = tid & 31;
    int wm = wid >> 1, wn = wid & 1;         // 4 m-slices x 2 n-slices
    int row0 = blockIdx.y * 64, col0 = blockIdx.x * 128;

    wmma::fragment<wmma::accumulator, 16, 16, 16, float> acc[4];
#pragma unroll
    for (int ni = 0; ni < 4; ni++) wmma::fill_fragment(acc[ni], 0.0f);

    int KT = (K + 31) >> 5;

    auto loadA = [&](int kt, int buf) {
        int k0 = kt << 5;
#pragma unroll
        for (int i = 0; i < 2; i++) {
            int v = tid + (i << 8);             // 0..511
            int r = v >> 3, c = (v & 7) << 2;
            int gr = row0 + r;
            float4 a = make_float4(0.f, 0.f, 0.f, 0.f);
            if (gr < M && k0 + c < K) a = *(const float4*)(A + (size_t)gr * lda + k0 + c);
            int idx = buf * 2560 + r * 40 + c;
            split4(a, &Ah[idx], &Am[idx]);
        }
    };
    auto loadB = [&](int kt, int buf) {
        int k0 = kt << 5;
#pragma unroll
        for (int i = 0; i < 4; i++) {
            int v = tid + (i << 8);             // 0..1023
            int r = v >> 5, c = (v & 31) << 2;
            int gc = col0 + c;
            float4 b = make_float4(0.f, 0.f, 0.f, 0.f);
            if (gc < N && k0 + r < K) b = *(const float4*)(B + (size_t)(k0 + r) * N + gc);
            int idx = buf * 4352 + r * 136 + c;
            split4(b, &Bh[idx], &Bm[idx]);
        }
    };

    loadA(0, 0); loadB(0, 0);
    __syncthreads();
    for (int kt = 0; kt < KT; kt++) {
        int buf = kt & 1;
        if (kt + 1 < KT) { loadA(kt + 1, buf ^ 1); loadB(kt + 1, buf ^ 1); }
#pragma unroll
        for (int ks = 0; ks < 2; ks++) {
            wmma::fragment<wmma::matrix_a, 16, 16, 16, __nv_bfloat16, wmma::row_major> ah, am;
            wmma::fragment<wmma::matrix_b, 16, 16, 16, __nv_bfloat16, wmma::row_major> bh[4], bm[4];
            int aoff = buf * 2560 + (wm * 16) * 40 + ks * 16;
            wmma::load_matrix_sync(ah, &Ah[aoff], 40);
            wmma::load_matrix_sync(am, &Am[aoff], 40);
#pragma unroll
            for (int ni = 0; ni < 4; ni++) {
                int boff = buf * 4352 + (ks * 16) * 136 + wn * 64 + ni * 16;
                wmma::load_matrix_sync(bh[ni], &Bh[boff], 136);
                wmma::load_matrix_sync(bm[ni], &Bm[boff], 136);
            }
#pragma unroll
            for (int ni = 0; ni < 4; ni++) {
                wmma::mma_sync(acc[ni], am, bh[ni], acc[ni]);
                wmma::mma_sync(acc[ni], ah, bm[ni], acc[ni]);
                wmma::mma_sync(acc[ni], ah, bh[ni], acc[ni]);
            }
        }
        __syncthreads();
    }

    // epilogue: per-warp staging (8 warps x 320 floats = 10.2KB, reuses smem front)
    float* epi = (float*)sm_raw + wid * 320;
#pragma unroll
    for (int ni = 0; ni < 4; ni++) {
        wmma::store_matrix_sync(epi, acc[ni], 20, wmma::mem_row_major);
        __syncwarp();
        int r = lane >> 1, cb = (lane & 1) * 8;
        int m = row0 + wm * 16 + r;
        int n0 = col0 + wn * 64 + ni * 16 + cb;
        if (m < M && n0 < N) {
            float rs = rowscale ? rowscale[m] : 1.0f;
            float4 v0 = *(float4*)&epi[r * 20 + cb];
            float4 v1 = *(float4*)&epi[r * 20 + cb + 4];
            if (Cin) {
                float4 c0 = *(const float4*)(Cin + (size_t)m * ldc + n0);
                float4 c1 = *(const float4*)(Cin + (size_t)m * ldc + n0 + 4);
                v0.x += c0.x; v0.y += c0.y; v0.z += c0.z; v0.w += c0.w;
                v1.x += c1.x; v1.y += c1.y; v1.z += c1.z; v1.w += c1.w;
            }
            if (bias) {
                float4 b0 = *(const float4*)(bias + n0);
                float4 b1 = *(const float4*)(bias + n0 + 4);
                v0.x += rs * b0.x; v0.y += rs * b0.y; v0.z += rs * b0.z; v0.w += rs * b0.w;
                v1.x += rs * b1.x; v1.y += rs * b1.y; v1.z += rs * b1.z; v1.w += rs * b1.w;
            }
            if (relu) {
                v0.x = fmaxf(v0.x, 0.f); v0.y = fmaxf(v0.y, 0.f);
                v0.z = fmaxf(v0.z, 0.f); v0.w = fmaxf(v0.w, 0.f);
                v1.x = fmaxf(v1.x, 0.f); v1.y = fmaxf(v1.y, 0.f);
                v1.z = fmaxf(v1.z, 0.f); v1.w = fmaxf(v1.w, 0.f);
            }
            *(float4*)(D + (size_t)m * ldd + n0)     = v0;
            *(float4*)(D + (size_t)m * ldd + n0 + 4) = v1;
        }
        __syncwarp();
    }
}

// ---------------- fused EA edge pass (PQ interleaved, 4x batched) ----------------
// S[i] = sum_neighbors relu( PQ[i,0:128] + PQ[src,128:256] + (ea[rid]@W1e + b1) )
__global__ __launch_bounds__(256)
void k_edge_f(const float* __restrict__ PQ,
              const float* __restrict__ EA, const float* __restrict__ W1e,
              const float* __restrict__ b1, float* __restrict__ S) {
    __shared__ float sw[16 * 128];
    __shared__ float sb[128];
    for (int v = threadIdx.x; v < 2048; v += blockDim.x) sw[v] = W1e[v];
    for (int v = threadIdx.x; v < 128; v += blockDim.x) sb[v] = b1[v];
    __syncthreads();
    int lane = threadIdx.x & 31;
    int f = lane * 4;
    float w[16][4];
#pragma unroll
    for (int k = 0; k < 16; k++) {
        float4 t = *(const float4*)&sw[k * 128 + f];
        w[k][0] = t.x; w[k][1] = t.y; w[k][2] = t.z; w[k][3] = t.w;
    }
    float4 bb = *(const float4*)&sb[f];

    int i = (blockIdx.x * blockDim.x + threadIdx.x) >> 5;
    if (i >= NN) return;
    float4 p = *(const float4*)(PQ + (size_t)i * 256 + f);
    float4 acc = make_float4(0.f, 0.f, 0.f, 0.f);
    int s = g_off[i], s1 = g_off[i + 1];

    for (; s + 4 <= s1; s += 4) {
        int src[4], rid[4];
#pragma unroll
        for (int j = 0; j < 4; j++) { src[j] = g_csr_src[s + j]; rid[j] = g_csr_rid[s + j]; }
        float4 q[4]; float ev[4];
#pragma unroll
        for (int j = 0; j < 4; j++) {
            q[j] = *(const float4*)(PQ + (size_t)src[j] * 256 + 128 + f);
            ev[j] = (lane < 16) ? EA[(size_t)rid[j] * 16 + lane] : 0.0f;
        }
#pragma unroll
        for (int j = 0; j < 4; j++) {
            float4 r = bb;
#pragma unroll
            for (int k = 0; k < 16; k++) {
                float a = __shfl_sync(0xffffffffu, ev[j], k);
                r.x += a * w[k][0]; r.y += a * w[k][1];
                r.z += a * w[k][2]; r.w += a * w[k][3];
            }
            acc.x += fmaxf(p.x + q[j].x + r.x, 0.f);
            acc.y += fmaxf(p.y + q[j].y + r.y, 0.f);
            acc.z += fmaxf(p.z + q[j].z + r.z, 0.f);
            acc.w += fmaxf(p.w + q[j].w + r.w, 0.f);
        }
    }
    for (; s < s1; s++) {
        int src = g_csr_src[s];
        int rid = g_csr_rid[s];
        float val = (lane < 16) ? EA[(size_t)rid * 16 + lane] : 0.0f;
        float4 q = *(const float4*)(PQ + (size_t)src * 256 + 128 + f);
        float4 r = bb;
#pragma unroll
        for (int k = 0; k < 16; k++) {
            float a = __shfl_sync(0xffffffffu, val, k);
            r.x += a * w[k][0]; r.y += a * w[k][1];
            r.z += a * w[k][2]; r.w += a * w[k][3];
        }
        acc.x += fmaxf(p.x + q.x + r.x, 0.f);
        acc.y += fmaxf(p.y + q.y + r.y, 0.f);
        acc.z += fmaxf(p.z + q.z + r.z, 0.f);
        acc.w += fmaxf(p.w + q.w + r.w, 0.f);
    }
    *(float4*)(S + (size_t)i * HD + f) = acc;
}

// ---------------- TAG propagation (norm folded via dis), ld = 512, 4x batched ---------
__global__ __launch_bounds__(256)
void k_prop(const float* __restrict__ Xc, float* __restrict__ Xn) {
    int i = (blockIdx.x * blockDim.x + threadIdx.x) >> 5;
    if (i >= NN) return;
    int lane = threadIdx.x & 31;
    int f = lane * 4;
    float4 acc = make_float4(0.f, 0.f, 0.f, 0.f);
    int s = g_off[i], s1 = g_off[i + 1];

    for (; s + 4 <= s1; s += 4) {
        int src[4];
#pragma unroll
        for (int j = 0; j < 4; j++) src[j] = g_csr_src[s + j];
        float nm[4]; float4 h[4];
#pragma unroll
        for (int j = 0; j < 4; j++) {
            nm[j] = __ldg(&g_dis[src[j]]);
            h[j] = *(const float4*)(Xc + (size_t)src[j] * 512 + f);
        }
#pragma unroll
        for (int j = 0; j < 4; j++) {
            acc.x += nm[j] * h[j].x; acc.y += nm[j] * h[j].y;
            acc.z += nm[j] * h[j].z; acc.w += nm[j] * h[j].w;
        }
    }
    for (; s < s1; s++) {
        int src = g_csr_src[s];
        float nm = __ldg(&g_dis[src]);
        float4 h = *(const float4*)(Xc + (size_t)src * 512 + f);
        acc.x += nm * h.x; acc.y += nm * h.y;
        acc.z += nm * h.z; acc.w += nm * h.w;
    }
    float di = __ldg(&g_dis[i]);
    acc.x *= di; acc.y *= di; acc.z *= di; acc.w *= di;
    *(float4*)(Xn + (size_t)i * 512 + f) = acc;
}

// ---------------- final output: out[i] = C[i]@W2 + deg[i]*b2  (N=16) ----------------
__global__ __launch_bounds__(256)
void k_out(const float* __restrict__ C, const float* __restrict__ W2,
           const float* __restrict__ b2, float* __restrict__ out) {
    __shared__ float sw[128 * 16];
    __shared__ float sb[16];
    for (int v = threadIdx.x; v < 2048; v += blockDim.x) sw[v] = W2[v];
    if (threadIdx.x < 16) sb[threadIdx.x] = b2[threadIdx.x];
    __syncthreads();
    int gt = blockIdx.x * blockDim.x + threadIdx.x;
    int i = gt >> 5;
    if (i >= NN) return;
    int lane = threadIdx.x & 31, f = lane * 4;
    float4 c = *(const float4*)(C + (size_t)i * HD + f);
    float o[16];
#pragma unroll
    for (int t = 0; t < 16; t++) o[t] = 0.0f;
    float cv[4] = {c.x, c.y, c.z, c.w};
#pragma unroll
    for (int j = 0; j < 4; j++) {
        const float* wr = &sw[(f + j) * 16];
        float cj = cv[j];
#pragma unroll
        for (int t = 0; t < 16; t++) o[t] += cj * wr[t];
    }
#pragma unroll
    for (int off = 16; off > 0; off >>= 1)
#pragma unroll
        for (int t = 0; t < 16; t++) o[t] += __shfl_xor_sync(0xffffffffu, o[t], off);
    if (lane < 16)
        out[(size_t)i * 16 + lane] = o[lane] + g_degf[i] * sb[lane];
}

// ---------------- host ----------------
static void gemm(const float* A, int lda, const float* B, long bStride,
                 float* D, int ldd, long dStride,
                 const float* Cin, int ldc, const float* bias, const float* rowscale,
                 int M, int K, int N, int relu, int batch) {
    dim3 grid((N + 127) / 128, (M + 63) / 64, batch);
    k_gemm_tc<<<grid, 256, GEMM_SMEM>>>(A, lda, B, bStride, D, ldd, dStride,
                                        Cin, ldc, bias, rowscale, M, K, N, relu);
}

extern "C" void kernel_launch(void* const* d_in, const int* in_sizes, int n_in,
                              void* d_out, int out_size) {
    const float* x         = (const float*)d_in[0];
    const float* mask      = (const float*)d_in[1];
    const float* edge_attr = (const float*)d_in[2];
    const int* edge_index;
    int base;
    if (in_sizes[3] == 2 * EE) {
        edge_index = (const int*)d_in[3];
        base = 4;
    } else {
        edge_index = (const int*)d_in[n_in - 1];
        base = 3;
    }
    const float* m_w1   = (const float*)d_in[base + 0];
    const float* m_b1   = (const float*)d_in[base + 1];
    const float* m_w2   = (const float*)d_in[base + 2];
    const float* m_b2   = (const float*)d_in[base + 3];
    const float* ea0_w1 = (const float*)d_in[base + 4];
    const float* ea0_b1 = (const float*)d_in[base + 5];
    const float* ea0_w2 = (const float*)d_in[base + 6];
    const float* ea0_b2 = (const float*)d_in[base + 7];
    const float* tag0_w = (const float*)d_in[base + 8];
    const float* tag0_b = (const float*)d_in[base + 9];
    const float* ea1_w1 = (const float*)d_in[base + 10];
    const float* ea1_b1 = (const float*)d_in[base + 11];
    const float* ea1_w2 = (const float*)d_in[base + 12];
    const float* ea1_b2 = (const float*)d_in[base + 13];
    const float* tag1_w = (const float*)d_in[base + 14];
    const float* tag1_b = (const float*)d_in[base + 15];
    const float* ea2_w1 = (const float*)d_in[base + 16];
    const float* ea2_b1 = (const float*)d_in[base + 17];
    const float* ea2_w2 = (const float*)d_in[base + 18];
    const float* ea2_b2 = (const float*)d_in[base + 19];

    float *pPQ, *pC, *pH, *pX, *ph16, *pdegf;
    cudaGetSymbolAddress((void**)&pPQ, g_PQ);
    cudaGetSymbolAddress((void**)&pC, g_C);
    cudaGetSymbolAddress((void**)&pH, g_H);
    cudaGetSymbolAddress((void**)&pX, g_X);
    cudaGetSymbolAddress((void**)&ph16, g_h16);
    cudaGetSymbolAddress((void**)&pdegf, g_degf);

    static int smem_set = 0;
    if (!smem_set) {
        cudaFuncSetAttribute(k_gemm_tc, cudaFuncAttributeMaxDynamicSharedMemorySize, GEMM_SMEM);
        smem_set = 1;
    }

    const int EB = 2500;              // 20000 node-warps / 8 warps per block

    // launch order puts the EA0 projection GEMM at slot 3 (ncu capture position)
    k_mask<<<EB, 256>>>(mask, x, m_w1, m_b1, m_w2, m_b2, ph16);   // 0 (zeroes g_deg)
    k_hist<<<(EE + 255) / 256, 256>>>(edge_index);                 // 1
    k_scan<<<1, 1024>>>();                                         // 2
    gemm(ph16, 16, ea0_w1, 16 * 128, pPQ, 256, 128, nullptr, 0, nullptr, nullptr,
         NN, 16, 128, 0, 2);                                       // 3 <- ncu
    k_fill<<<(EE + 255) / 256, 256>>>(edge_index);                 // 4

    // ---- EA0 ----
    k_edge_f<<<EB, 256>>>(pPQ, edge_attr, ea0_w1 + 32 * 128, ea0_b1, pC);
    gemm(pC, 128, ea0_w2, 0, pX, 512, 0, nullptr, 0, ea0_b2, pdegf, NN, 128, 128, 1, 1);

    // ---- TAG0 ----
    k_prop<<<EB, 256>>>(pX,       pX + 128);
    k_prop<<<EB, 256>>>(pX + 128, pX + 256);
    k_prop<<<EB, 256>>>(pX + 256, pX + 384);
    gemm(pX, 512, tag0_w, 0, pH, 128, 0, nullptr, 0, tag0_b, nullptr, NN, 512, 128, 1, 1);

    // ---- EA1 ----
    gemm(pH, 128, ea1_w1, 128 * 128, pPQ, 256, 128, nullptr, 0, nullptr, nullptr,
         NN, 128, 128, 0, 2);
    k_edge_f<<<EB, 256>>>(pPQ, edge_attr, ea1_w1 + 256 * 128, ea1_b1, pC);
    gemm(pC, 128, ea1_w2, 0, pX, 512, 0, nullptr, 0, ea1_b2, pdegf, NN, 128, 128, 1, 1);

    // ---- TAG1 ----
    k_prop<<<EB, 256>>>(pX,       pX + 128);
    k_prop<<<EB, 256>>>(pX + 128, pX + 256);
    k_prop<<<EB, 256>>>(pX + 256, pX + 384);
    gemm(pX, 512, tag1_w, 0, pH, 128, 0, nullptr, 0, tag1_b, nullptr, NN, 512, 128, 1, 1);

    // ---- EA2 (final) ----
    gemm(pH, 128, ea2_w1, 128 * 128, pPQ, 256, 128, nullptr, 0, nullptr, nullptr,
         NN, 128, 128, 0, 2);
    k_edge_f<<<EB, 256>>>(pPQ, edge_attr, ea2_w1 + 256 * 128, ea2_b1, pC);
    k_out<<<EB, 256>>>(pC, ea2_w2, ea2_b2, (float*)d_out);
}